// round 7
// baseline (speedup 1.0000x reference)
#include <cuda_runtime.h>
#include <cuda_bf16.h>
#include <math.h>
#include <stdint.h>

#define NB 4096      // boxes
#define NE 32768     // edges
#define OD 2048      // obj_dim
#define FD 2432      // feats_dim

// ---------------- static scratch (no cudaMalloc allowed) ----------------
__device__ float g_box_att[(size_t)NB * OD];
__device__ float g_rel_att[(size_t)NE * OD];
__device__ float g_logit[2 * NE];
__device__ float g_alpha[2 * NE];
__device__ float g_nmax[2 * NB];
__device__ float g_denom[2 * NB];
__device__ float g_salpha[2 * NB];
__device__ float g_wsum[2ull * NB * FD];
__device__ float g_acc[(size_t)NB * OD];

// bf16 hi/lo split buffers
__device__ __nv_bfloat16 g_relh[(size_t)NE * FD], g_rell[(size_t)NE * FD];
__device__ __nv_bfloat16 g_boxh[(size_t)NB * OD], g_boxl[(size_t)NB * OD];
__device__ __nv_bfloat16 g_wsh[2ull * NB * FD],  g_wsl[2ull * NB * FD];
__device__ __nv_bfloat16 g_Wabh[(size_t)OD * OD], g_Wabl[(size_t)OD * OD];
__device__ __nv_bfloat16 g_Warh[(size_t)FD * OD], g_Warl[(size_t)FD * OD];
__device__ __nv_bfloat16 g_Wbh[(size_t)OD * OD],  g_Wbl[(size_t)OD * OD];
__device__ __nv_bfloat16 g_Wsh[(size_t)FD * OD],  g_Wsl[(size_t)FD * OD];
__device__ __nv_bfloat16 g_Woh[(size_t)FD * OD],  g_Wol[(size_t)FD * OD];

// ---------------- init ----------------
__global__ void init_kernel() {
    size_t idx = (size_t)blockIdx.x * blockDim.x + threadIdx.x;
    size_t stride = (size_t)gridDim.x * blockDim.x;
    for (size_t i = idx; i < 2ull * NB * FD; i += stride) g_wsum[i] = 0.f;
    for (size_t i = idx; i < 2 * NB; i += stride) {
        g_denom[i] = 0.f;
        g_nmax[i] = -INFINITY;
    }
}

// ---------------- fp32 -> bf16 hi/lo split ----------------
__global__ void split_kernel(const float* __restrict__ src,
                             __nv_bfloat16* __restrict__ hi,
                             __nv_bfloat16* __restrict__ lo, long n) {
    long i = ((long)blockIdx.x * blockDim.x + threadIdx.x) * 4;
    if (i >= n) return;
    float4 v = *(const float4*)(src + i);
    __nv_bfloat16 h[4], l[4];
    h[0] = __float2bfloat16_rn(v.x); l[0] = __float2bfloat16_rn(v.x - __bfloat162float(h[0]));
    h[1] = __float2bfloat16_rn(v.y); l[1] = __float2bfloat16_rn(v.y - __bfloat162float(h[1]));
    h[2] = __float2bfloat16_rn(v.z); l[2] = __float2bfloat16_rn(v.z - __bfloat162float(h[2]));
    h[3] = __float2bfloat16_rn(v.w); l[3] = __float2bfloat16_rn(v.w - __bfloat162float(h[3]));
    *(uint2*)(hi + i) = *(uint2*)h;
    *(uint2*)(lo + i) = *(uint2*)l;
}

// ---------------- MMA helpers ----------------
__device__ __forceinline__ uint32_t sptr(const void* p) {
    return (uint32_t)__cvta_generic_to_shared(p);
}
__device__ __forceinline__ void cpa16(uint32_t dst, const void* src) {
    asm volatile("cp.async.cg.shared.global [%0], [%1], 16;" :: "r"(dst), "l"(src));
}
__device__ __forceinline__ void ldm4(uint32_t* r, uint32_t a) {
    asm volatile("ldmatrix.sync.aligned.m8n8.x4.shared.b16 {%0,%1,%2,%3}, [%4];"
        : "=r"(r[0]), "=r"(r[1]), "=r"(r[2]), "=r"(r[3]) : "r"(a));
}
__device__ __forceinline__ void ldm4t(uint32_t* r, uint32_t a) {
    asm volatile("ldmatrix.sync.aligned.m8n8.x4.trans.shared.b16 {%0,%1,%2,%3}, [%4];"
        : "=r"(r[0]), "=r"(r[1]), "=r"(r[2]), "=r"(r[3]) : "r"(a));
}
__device__ __forceinline__ void mma16816(float* c, const uint32_t* a, const uint32_t* b) {
    asm volatile("mma.sync.aligned.m16n8k16.row.col.f32.bf16.bf16.f32 "
        "{%0,%1,%2,%3}, {%4,%5,%6,%7}, {%8,%9}, {%0,%1,%2,%3};"
        : "+f"(c[0]), "+f"(c[1]), "+f"(c[2]), "+f"(c[3])
        : "r"(a[0]), "r"(a[1]), "r"(a[2]), "r"(a[3]), "r"(b[0]), "r"(b[1]));
}

// ---------------- bf16 hi/lo tensor-core GEMM, cp.async double-buffered ----------
// CTA tile 128x128, BK=32, 8 warps (2x4), warp tile 64x32.
#define LDA 40
#define LDB 136
#define STG_A (128 * LDA)          // elems per A matrix per stage (5120)
#define STG_B (32 * LDB)           // elems per B matrix per stage (4352)
#define STG_ELEMS (2 * STG_A + 2 * STG_B)   // Ah|Al|Bh|Bl = 18944 elems
#define SMEM_GEMM (2 * STG_ELEMS * 2)       // 75776 bytes

__device__ __forceinline__ void load_stage(__nv_bfloat16* s,
                                           const __nv_bfloat16* Ah, const __nv_bfloat16* Al,
                                           const __nv_bfloat16* Bh, const __nv_bfloat16* Bl,
                                           int K, int N, int bm, int bn, int k0, int tid) {
    __nv_bfloat16* ah = s;
    __nv_bfloat16* al = s + STG_A;
    __nv_bfloat16* bh = s + 2 * STG_A;
    __nv_bfloat16* bl = s + 2 * STG_A + STG_B;
    #pragma unroll
    for (int t = 0; t < 2; t++) {
        int u = tid + (t << 8);
        int r = u >> 2, cg = (u & 3) << 3;       // A: 128 rows x 32 cols
        size_t ga = (size_t)(bm + r) * K + k0 + cg;
        cpa16(sptr(ah + r * LDA + cg), Ah + ga);
        cpa16(sptr(al + r * LDA + cg), Al + ga);
        int rb = u >> 4, cb = (u & 15) << 3;     // B: 32 rows x 128 cols
        size_t gb = (size_t)(k0 + rb) * N + bn + cb;
        cpa16(sptr(bh + rb * LDB + cb), Bh + gb);
        cpa16(sptr(bl + rb * LDB + cb), Bl + gb);
    }
    asm volatile("cp.async.commit_group;");
}

__global__ __launch_bounds__(256, 2)
void mma_gemm(const __nv_bfloat16* __restrict__ Ah, const __nv_bfloat16* __restrict__ Al,
              const __nv_bfloat16* __restrict__ Bh, const __nv_bfloat16* __restrict__ Bl,
              const float* __restrict__ Cin, float* __restrict__ Cout,
              int M, int N, int K, int do_relu) {
    extern __shared__ __nv_bfloat16 smem[];

    const int tid  = threadIdx.x;
    const int lane = tid & 31;
    const int wid  = tid >> 5;
    const int wm   = wid & 1;       // 0..1 -> 64-row slab
    const int wn   = wid >> 1;      // 0..3 -> 32-col slab
    const int bm   = blockIdx.y * 128;
    const int bn   = blockIdx.x * 128;

    float acc[4][4][4];
    #pragma unroll
    for (int i = 0; i < 4; i++)
        #pragma unroll
        for (int j = 0; j < 4; j++)
            #pragma unroll
            for (int q = 0; q < 4; q++) acc[i][j][q] = 0.f;

    const int NC = K >> 5;
    load_stage(smem, Ah, Al, Bh, Bl, K, N, bm, bn, 0, tid);

    for (int c = 0; c < NC; c++) {
        if (c + 1 < NC) {
            load_stage(smem + ((c + 1) & 1) * STG_ELEMS, Ah, Al, Bh, Bl,
                       K, N, bm, bn, (c + 1) << 5, tid);
            asm volatile("cp.async.wait_group 1;");
        } else {
            asm volatile("cp.async.wait_group 0;");
        }
        __syncthreads();

        __nv_bfloat16* s = smem + (c & 1) * STG_ELEMS;
        __nv_bfloat16* sAh = s;
        __nv_bfloat16* sAl = s + STG_A;
        __nv_bfloat16* sBh = s + 2 * STG_A;
        __nv_bfloat16* sBl = s + 2 * STG_A + STG_B;

        #pragma unroll
        for (int ks = 0; ks < 32; ks += 16) {
            uint32_t bh[2][4], bl[2][4];
            #pragma unroll
            for (int nh = 0; nh < 2; nh++) {
                int rr = ks + (lane & 15);
                int cc = wn * 32 + nh * 16 + ((lane >> 4) << 3);
                ldm4t(bh[nh], sptr(&sBh[rr * LDB + cc]));
                ldm4t(bl[nh], sptr(&sBl[rr * LDB + cc]));
            }
            #pragma unroll
            for (int mt = 0; mt < 4; mt++) {
                uint32_t ah[4], al[4];
                int ar = wm * 64 + mt * 16 + (lane & 15);
                int ac = ks + ((lane >> 4) << 3);
                ldm4(ah, sptr(&sAh[ar * LDA + ac]));
                ldm4(al, sptr(&sAl[ar * LDA + ac]));
                #pragma unroll
                for (int nt = 0; nt < 4; nt++) {
                    const uint32_t* ph = &bh[nt >> 1][(nt & 1) * 2];
                    const uint32_t* pl = &bl[nt >> 1][(nt & 1) * 2];
                    mma16816(acc[mt][nt], ah, ph);   // hi*hi
                    mma16816(acc[mt][nt], ah, pl);   // hi*lo
                    mma16816(acc[mt][nt], al, ph);   // lo*hi
                }
            }
        }
        __syncthreads();
    }

    // epilogue
    const int r0 = bm + wm * 64;
    const int c0 = bn + wn * 32;
    #pragma unroll
    for (int mt = 0; mt < 4; mt++) {
        #pragma unroll
        for (int nt = 0; nt < 4; nt++) {
            int row = r0 + mt * 16 + (lane >> 2);
            int col = c0 + nt * 8 + ((lane & 3) << 1);
            float2 v01 = make_float2(acc[mt][nt][0], acc[mt][nt][1]);
            float2 v23 = make_float2(acc[mt][nt][2], acc[mt][nt][3]);
            if (Cin) {
                float2 c1 = *(const float2*)(Cin + (size_t)row * N + col);
                float2 c2 = *(const float2*)(Cin + (size_t)(row + 8) * N + col);
                v01.x += c1.x; v01.y += c1.y;
                v23.x += c2.x; v23.y += c2.y;
            }
            if (do_relu) {
                v01.x = fmaxf(v01.x, 0.f); v01.y = fmaxf(v01.y, 0.f);
                v23.x = fmaxf(v23.x, 0.f); v23.y = fmaxf(v23.y, 0.f);
            }
            *(float2*)(Cout + (size_t)row * N + col)       = v01;
            *(float2*)(Cout + (size_t)(row + 8) * N + col) = v23;
        }
    }
}

// ---------------- logits ----------------
__global__ __launch_bounds__(256)
void logit_kernel(const int* __restrict__ sub, const int* __restrict__ obj,
                  const float* __restrict__ b_a1, const float* __restrict__ Wa2,
                  const float* __restrict__ b_a2) {
    const int e = blockIdx.x;
    const int tid = threadIdx.x;
    const int s = sub[e], o = obj[e];

    const float4* ra = (const float4*)(g_rel_att + (size_t)e * OD);
    const float4* bs = (const float4*)(g_box_att + (size_t)s * OD);
    const float4* bo = (const float4*)(g_box_att + (size_t)o * OD);
    const float4* bb = (const float4*)b_a1;
    const float4* w  = (const float4*)Wa2;

    float ps = 0.f, po = 0.f;
    for (int i = tid; i < OD / 4; i += blockDim.x) {
        float4 r = ra[i], b1 = bs[i], b2 = bo[i], bi = bb[i], wv = w[i];
        ps = fmaf(fmaxf(r.x + b1.x + bi.x, 0.f), wv.x, ps);
        ps = fmaf(fmaxf(r.y + b1.y + bi.y, 0.f), wv.y, ps);
        ps = fmaf(fmaxf(r.z + b1.z + bi.z, 0.f), wv.z, ps);
        ps = fmaf(fmaxf(r.w + b1.w + bi.w, 0.f), wv.w, ps);
        po = fmaf(fmaxf(r.x + b2.x + bi.x, 0.f), wv.x, po);
        po = fmaf(fmaxf(r.y + b2.y + bi.y, 0.f), wv.y, po);
        po = fmaf(fmaxf(r.z + b2.z + bi.z, 0.f), wv.z, po);
        po = fmaf(fmaxf(r.w + b2.w + bi.w, 0.f), wv.w, po);
    }
    __shared__ float red[2][8];
    #pragma unroll
    for (int off = 16; off > 0; off >>= 1) {
        ps += __shfl_down_sync(0xffffffffu, ps, off);
        po += __shfl_down_sync(0xffffffffu, po, off);
    }
    if ((tid & 31) == 0) { red[0][tid >> 5] = ps; red[1][tid >> 5] = po; }
    __syncthreads();
    if (tid == 0) {
        float a = 0.f, b = 0.f;
        #pragma unroll
        for (int wi = 0; wi < 8; wi++) { a += red[0][wi]; b += red[1][wi]; }
        float ba2 = b_a2[0];
        g_logit[e]      = a + ba2;
        g_logit[NE + e] = b + ba2;
    }
}

// ---------------- segment softmax ----------------
__device__ __forceinline__ void atomicMaxF(float* addr, float v) {
    if (v >= 0.f) atomicMax((int*)addr, __float_as_int(v));
    else          atomicMin((unsigned int*)addr, __float_as_uint(v));
}

__global__ void segmax_kernel(const int* __restrict__ sub, const int* __restrict__ obj) {
    int e = blockIdx.x * blockDim.x + threadIdx.x;
    if (e >= NE) return;
    atomicMaxF(&g_nmax[sub[e]], g_logit[e]);
    atomicMaxF(&g_nmax[NB + obj[e]], g_logit[NE + e]);
}

__global__ void expsum_kernel(const int* __restrict__ sub, const int* __restrict__ obj) {
    int e = blockIdx.x * blockDim.x + threadIdx.x;
    if (e >= NE) return;
    int s = sub[e], o = obj[e];
    float es = expf(g_logit[e] - g_nmax[s]);
    float eo = expf(g_logit[NE + e] - g_nmax[NB + o]);
    g_alpha[e] = es;
    g_alpha[NE + e] = eo;
    atomicAdd(&g_denom[s], es);
    atomicAdd(&g_denom[NB + o], eo);
}

__global__ void salpha_kernel() {
    int i = blockIdx.x * blockDim.x + threadIdx.x;
    if (i >= 2 * NB) return;
    float d = g_denom[i];
    g_salpha[i] = d / (d + 1e-9f);
}

// ---------------- weighted scatter ----------------
__global__ __launch_bounds__(256)
void scatter_kernel(const float* __restrict__ rel, const int* __restrict__ sub,
                    const int* __restrict__ obj) {
    const int e = blockIdx.x;
    const int tid = threadIdx.x;
    const int s = sub[e], o = obj[e];
    const float as = g_alpha[e] / (g_denom[s] + 1e-9f);
    const float ao = g_alpha[NE + e] / (g_denom[NB + o] + 1e-9f);

    const float4* r = (const float4*)(rel + (size_t)e * FD);
    float* ws = g_wsum + (size_t)s * FD;
    float* wo = g_wsum + ((size_t)NB + o) * FD;
    for (int i = tid; i < FD / 4; i += blockDim.x) {
        float4 v = r[i];
        int c = i * 4;
        atomicAdd(&ws[c + 0], as * v.x);
        atomicAdd(&ws[c + 1], as * v.y);
        atomicAdd(&ws[c + 2], as * v.z);
        atomicAdd(&ws[c + 3], as * v.w);
        atomicAdd(&wo[c + 0], ao * v.x);
        atomicAdd(&wo[c + 1], ao * v.y);
        atomicAdd(&wo[c + 2], ao * v.z);
        atomicAdd(&wo[c + 3], ao * v.w);
    }
}

// ---------------- acc init with biases ----------------
__global__ void biasinit_kernel(const float* __restrict__ b_box,
                                const float* __restrict__ b_sub,
                                const float* __restrict__ b_obj) {
    size_t idx = (size_t)blockIdx.x * blockDim.x + threadIdx.x;
    if (idx >= (size_t)NB * OD) return;
    int i = (int)(idx / OD);
    int n = (int)(idx % OD);
    g_acc[idx] = b_box[n] + g_salpha[i] * b_sub[n] + g_salpha[NB + i] * b_obj[n];
}

// ---------------- launch ----------------
static inline void split(const float* src, __nv_bfloat16* hi, __nv_bfloat16* lo, long n) {
    split_kernel<<<(int)((n / 4 + 255) / 256), 256>>>(src, hi, lo, n);
}

extern "C" void kernel_launch(void* const* d_in, const int* in_sizes, int n_in,
                              void* d_out, int out_size) {
    const float* box_feats = (const float*)d_in[0];
    const float* rel_feats = (const float*)d_in[1];
    const int*   edge_sub  = (const int*)d_in[2];
    const int*   edge_obj  = (const int*)d_in[3];
    const float* W_box  = (const float*)d_in[4];
    const float* b_box  = (const float*)d_in[5];
    const float* W_sub  = (const float*)d_in[6];
    const float* b_sub  = (const float*)d_in[7];
    const float* W_obj  = (const float*)d_in[8];
    const float* b_obj  = (const float*)d_in[9];
    const float* Wa_box = (const float*)d_in[10];
    const float* Wa_rel = (const float*)d_in[11];
    const float* b_a1   = (const float*)d_in[12];
    const float* Wa2    = (const float*)d_in[13];
    const float* b_a2   = (const float*)d_in[14];
    float* out = (float*)d_out;

    float *box_att, *rel_att, *acc, *wsum;
    cudaGetSymbolAddress((void**)&box_att, g_box_att);
    cudaGetSymbolAddress((void**)&rel_att, g_rel_att);
    cudaGetSymbolAddress((void**)&acc, g_acc);
    cudaGetSymbolAddress((void**)&wsum, g_wsum);

    __nv_bfloat16 *relh, *rell, *boxh, *boxl, *wsh, *wsl;
    __nv_bfloat16 *Wabh, *Wabl, *Warh, *Warl, *Wbh, *Wbl, *Wsh, *Wsl, *Woh, *Wol;
    cudaGetSymbolAddress((void**)&relh, g_relh); cudaGetSymbolAddress((void**)&rell, g_rell);
    cudaGetSymbolAddress((void**)&boxh, g_boxh); cudaGetSymbolAddress((void**)&boxl, g_boxl);
    cudaGetSymbolAddress((void**)&wsh,  g_wsh);  cudaGetSymbolAddress((void**)&wsl,  g_wsl);
    cudaGetSymbolAddress((void**)&Wabh, g_Wabh); cudaGetSymbolAddress((void**)&Wabl, g_Wabl);
    cudaGetSymbolAddress((void**)&Warh, g_Warh); cudaGetSymbolAddress((void**)&Warl, g_Warl);
    cudaGetSymbolAddress((void**)&Wbh,  g_Wbh);  cudaGetSymbolAddress((void**)&Wbl,  g_Wbl);
    cudaGetSymbolAddress((void**)&Wsh,  g_Wsh);  cudaGetSymbolAddress((void**)&Wsl,  g_Wsl);
    cudaGetSymbolAddress((void**)&Woh,  g_Woh);  cudaGetSymbolAddress((void**)&Wol,  g_Wol);

    cudaFuncSetAttribute(mma_gemm, cudaFuncAttributeMaxDynamicSharedMemorySize, SMEM_GEMM);

    init_kernel<<<2048, 256>>>();

    split(box_feats, boxh, boxl, (long)NB * OD);
    split(rel_feats, relh, rell, (long)NE * FD);
    split(Wa_box, Wabh, Wabl, (long)OD * OD);
    split(Wa_rel, Warh, Warl, (long)FD * OD);
    split(W_box,  Wbh,  Wbl,  (long)OD * OD);
    split(W_sub,  Wsh,  Wsl,  (long)FD * OD);
    split(W_obj,  Woh,  Wol,  (long)FD * OD);

    // box_att = box_feats @ Wa_box
    mma_gemm<<<dim3(OD / 128, NB / 128), 256, SMEM_GEMM>>>(
        boxh, boxl, Wabh, Wabl, nullptr, box_att, NB, OD, OD, 0);
    // rel_att = rel_feats @ Wa_rel   (dominant)
    mma_gemm<<<dim3(OD / 128, NE / 128), 256, SMEM_GEMM>>>(
        relh, rell, Warh, Warl, nullptr, rel_att, NE, OD, FD, 0);

    logit_kernel<<<NE, 256>>>(edge_sub, edge_obj, b_a1, Wa2, b_a2);
    segmax_kernel<<<(NE + 255) / 256, 256>>>(edge_sub, edge_obj);
    expsum_kernel<<<(NE + 255) / 256, 256>>>(edge_sub, edge_obj);
    salpha_kernel<<<(2 * NB + 255) / 256, 256>>>();
    scatter_kernel<<<NE, 256>>>(rel_feats, edge_sub, edge_obj);

    split(wsum, wsh, wsl, 2L * NB * FD);

    biasinit_kernel<<<(int)(((size_t)NB * OD + 255) / 256), 256>>>(b_box, b_sub, b_obj);

    // acc += box_feats @ W_box ; acc += wsum_s @ W_sub ; out = relu(acc + wsum_o @ W_obj)
    mma_gemm<<<dim3(OD / 128, NB / 128), 256, SMEM_GEMM>>>(
        boxh, boxl, Wbh, Wbl, acc, acc, NB, OD, OD, 0);
    mma_gemm<<<dim3(OD / 128, NB / 128), 256, SMEM_GEMM>>>(
        wsh, wsl, Wsh, Wsl, acc, acc, NB, OD, FD, 0);
    mma_gemm<<<dim3(OD / 128, NB / 128), 256, SMEM_GEMM>>>(
        wsh + (size_t)NB * FD, wsl + (size_t)NB * FD, Woh, Wol, acc, out,
        NB, OD, FD, 1);
}

// round 8
// speedup vs baseline: 1.4657x; 1.4657x over previous
#include <cuda_runtime.h>
#include <cuda_bf16.h>
#include <math.h>
#include <stdint.h>

#define NB 4096      // boxes
#define NE 32768     // edges
#define OD 2048      // obj_dim
#define FD 2432      // feats_dim

// ---------------- static scratch (no cudaMalloc allowed) ----------------
__device__ float g_box_att[(size_t)NB * OD];
__device__ float g_rel_att[(size_t)NE * OD];
__device__ float g_logit[2 * NE];
__device__ float g_alpha[2 * NE];
__device__ float g_nmax[2 * NB];
__device__ float g_denom[2 * NB];
__device__ float g_salpha[2 * NB];
__device__ float g_wsum[2ull * NB * FD];
__device__ float g_acc[(size_t)NB * OD];

// bf16 hi/lo split buffers
__device__ __nv_bfloat16 g_relh[(size_t)NE * FD];                    // hi only (1-product GEMM)
__device__ __nv_bfloat16 g_boxh[(size_t)NB * OD], g_boxl[(size_t)NB * OD];
__device__ __nv_bfloat16 g_wsh[2ull * NB * FD],  g_wsl[2ull * NB * FD];
__device__ __nv_bfloat16 g_Wabh[(size_t)OD * OD], g_Wabl[(size_t)OD * OD];
__device__ __nv_bfloat16 g_Warh[(size_t)FD * OD];                    // hi only
__device__ __nv_bfloat16 g_Wbh[(size_t)OD * OD],  g_Wbl[(size_t)OD * OD];
__device__ __nv_bfloat16 g_Wsh[(size_t)FD * OD],  g_Wsl[(size_t)FD * OD];
__device__ __nv_bfloat16 g_Woh[(size_t)FD * OD],  g_Wol[(size_t)FD * OD];

// ---------------- init ----------------
__global__ void init_kernel() {
    size_t idx = (size_t)blockIdx.x * blockDim.x + threadIdx.x;
    size_t stride = (size_t)gridDim.x * blockDim.x;
    for (size_t i = idx; i < 2ull * NB * FD; i += stride) g_wsum[i] = 0.f;
    for (size_t i = idx; i < 2 * NB; i += stride) {
        g_denom[i] = 0.f;
        g_nmax[i] = -INFINITY;
    }
}

// ---------------- fp32 -> bf16 hi/lo split ----------------
__global__ void split_kernel(const float* __restrict__ src,
                             __nv_bfloat16* __restrict__ hi,
                             __nv_bfloat16* __restrict__ lo, long n) {
    long i = ((long)blockIdx.x * blockDim.x + threadIdx.x) * 4;
    if (i >= n) return;
    float4 v = *(const float4*)(src + i);
    __nv_bfloat16 h[4], l[4];
    h[0] = __float2bfloat16_rn(v.x); l[0] = __float2bfloat16_rn(v.x - __bfloat162float(h[0]));
    h[1] = __float2bfloat16_rn(v.y); l[1] = __float2bfloat16_rn(v.y - __bfloat162float(h[1]));
    h[2] = __float2bfloat16_rn(v.z); l[2] = __float2bfloat16_rn(v.z - __bfloat162float(h[2]));
    h[3] = __float2bfloat16_rn(v.w); l[3] = __float2bfloat16_rn(v.w - __bfloat162float(h[3]));
    *(uint2*)(hi + i) = *(uint2*)h;
    *(uint2*)(lo + i) = *(uint2*)l;
}

// hi-only variant (for the logit-path rel GEMM operands)
__global__ void splith_kernel(const float* __restrict__ src,
                              __nv_bfloat16* __restrict__ hi, long n) {
    long i = ((long)blockIdx.x * blockDim.x + threadIdx.x) * 4;
    if (i >= n) return;
    float4 v = *(const float4*)(src + i);
    __nv_bfloat16 h[4];
    h[0] = __float2bfloat16_rn(v.x);
    h[1] = __float2bfloat16_rn(v.y);
    h[2] = __float2bfloat16_rn(v.z);
    h[3] = __float2bfloat16_rn(v.w);
    *(uint2*)(hi + i) = *(uint2*)h;
}

// ---------------- MMA helpers ----------------
__device__ __forceinline__ uint32_t sptr(const void* p) {
    return (uint32_t)__cvta_generic_to_shared(p);
}
__device__ __forceinline__ void ldm4(uint32_t* r, uint32_t a) {
    asm volatile("ldmatrix.sync.aligned.m8n8.x4.shared.b16 {%0,%1,%2,%3}, [%4];"
        : "=r"(r[0]), "=r"(r[1]), "=r"(r[2]), "=r"(r[3]) : "r"(a));
}
__device__ __forceinline__ void ldm4t(uint32_t* r, uint32_t a) {
    asm volatile("ldmatrix.sync.aligned.m8n8.x4.trans.shared.b16 {%0,%1,%2,%3}, [%4];"
        : "=r"(r[0]), "=r"(r[1]), "=r"(r[2]), "=r"(r[3]) : "r"(a));
}
__device__ __forceinline__ void mma16816(float* c, const uint32_t* a, const uint32_t* b) {
    asm volatile("mma.sync.aligned.m16n8k16.row.col.f32.bf16.bf16.f32 "
        "{%0,%1,%2,%3}, {%4,%5,%6,%7}, {%8,%9}, {%0,%1,%2,%3};"
        : "+f"(c[0]), "+f"(c[1]), "+f"(c[2]), "+f"(c[3])
        : "r"(a[0]), "r"(a[1]), "r"(a[2]), "r"(a[3]), "r"(b[0]), "r"(b[1]));
}

// ---------------- bf16 tensor-core GEMM (NPROD = 3: hi/lo exact; 1: hi only) ---
// CTA tile 128x128, BK=32, 8 warps (2x4), warp tile 64x32.  (round-4 proven base)
#define LDA 40
#define LDB 136

template <int NPROD>
__global__ __launch_bounds__(256, 2)
void mma_gemm(const __nv_bfloat16* __restrict__ Ah, const __nv_bfloat16* __restrict__ Al,
              const __nv_bfloat16* __restrict__ Bh, const __nv_bfloat16* __restrict__ Bl,
              const float* __restrict__ Cin, float* __restrict__ Cout,
              int M, int N, int K, int do_relu) {
    __shared__ __nv_bfloat16 sAh[128 * LDA], sAl[128 * LDA];
    __shared__ __nv_bfloat16 sBh[32 * LDB],  sBl[32 * LDB];

    const int tid  = threadIdx.x;
    const int lane = tid & 31;
    const int wid  = tid >> 5;
    const int wm   = wid & 1;       // 0..1  -> 64-row slab
    const int wn   = wid >> 1;      // 0..3  -> 32-col slab
    const int bm   = blockIdx.y * 128;
    const int bn   = blockIdx.x * 128;

    float acc[4][4][4];
    #pragma unroll
    for (int i = 0; i < 4; i++)
        #pragma unroll
        for (int j = 0; j < 4; j++)
            #pragma unroll
            for (int q = 0; q < 4; q++) acc[i][j][q] = 0.f;

    for (int k0 = 0; k0 < K; k0 += 32) {
        #pragma unroll
        for (int p = 0; p < 2; p++) {
            int u  = tid + p * 256;
            int r  = u >> 2,  cg = (u & 3) << 3;     // A: 128 rows x 32 cols
            int rb = u >> 4,  cb = (u & 15) << 3;    // B: 32 rows x 128 cols
            *(uint4*)&sAh[r * LDA + cg]  = *(const uint4*)(Ah + (size_t)(bm + r) * K + k0 + cg);
            *(uint4*)&sBh[rb * LDB + cb] = *(const uint4*)(Bh + (size_t)(k0 + rb) * N + bn + cb);
            if (NPROD == 3) {
                *(uint4*)&sAl[r * LDA + cg]  = *(const uint4*)(Al + (size_t)(bm + r) * K + k0 + cg);
                *(uint4*)&sBl[rb * LDB + cb] = *(const uint4*)(Bl + (size_t)(k0 + rb) * N + bn + cb);
            }
        }
        __syncthreads();

        #pragma unroll
        for (int ks = 0; ks < 32; ks += 16) {
            uint32_t bh[2][4], bl[2][4];
            #pragma unroll
            for (int nh = 0; nh < 2; nh++) {
                int rr = ks + (lane & 15);
                int cc = wn * 32 + nh * 16 + ((lane >> 4) << 3);
                ldm4t(bh[nh], sptr(&sBh[rr * LDB + cc]));
                if (NPROD == 3) ldm4t(bl[nh], sptr(&sBl[rr * LDB + cc]));
            }
            #pragma unroll
            for (int mt = 0; mt < 4; mt++) {
                uint32_t ah[4], al[4];
                int ar = wm * 64 + mt * 16 + (lane & 15);
                int ac = ks + ((lane >> 4) << 3);
                ldm4(ah, sptr(&sAh[ar * LDA + ac]));
                if (NPROD == 3) ldm4(al, sptr(&sAl[ar * LDA + ac]));
                #pragma unroll
                for (int nt = 0; nt < 4; nt++) {
                    const uint32_t* ph = &bh[nt >> 1][(nt & 1) * 2];
                    mma16816(acc[mt][nt], ah, ph);           // hi*hi
                    if (NPROD == 3) {
                        const uint32_t* pl = &bl[nt >> 1][(nt & 1) * 2];
                        mma16816(acc[mt][nt], ah, pl);       // hi*lo
                        mma16816(acc[mt][nt], al, ph);       // lo*hi
                    }
                }
            }
        }
        __syncthreads();
    }

    // epilogue
    const int r0 = bm + wm * 64;
    const int c0 = bn + wn * 32;
    #pragma unroll
    for (int mt = 0; mt < 4; mt++) {
        #pragma unroll
        for (int nt = 0; nt < 4; nt++) {
            int row = r0 + mt * 16 + (lane >> 2);
            int col = c0 + nt * 8 + ((lane & 3) << 1);
            float2 v01 = make_float2(acc[mt][nt][0], acc[mt][nt][1]);
            float2 v23 = make_float2(acc[mt][nt][2], acc[mt][nt][3]);
            if (Cin) {
                float2 c1 = *(const float2*)(Cin + (size_t)row * N + col);
                float2 c2 = *(const float2*)(Cin + (size_t)(row + 8) * N + col);
                v01.x += c1.x; v01.y += c1.y;
                v23.x += c2.x; v23.y += c2.y;
            }
            if (do_relu) {
                v01.x = fmaxf(v01.x, 0.f); v01.y = fmaxf(v01.y, 0.f);
                v23.x = fmaxf(v23.x, 0.f); v23.y = fmaxf(v23.y, 0.f);
            }
            *(float2*)(Cout + (size_t)row * N + col)       = v01;
            *(float2*)(Cout + (size_t)(row + 8) * N + col) = v23;
        }
    }
}

// ---------------- logits ----------------
__global__ __launch_bounds__(256)
void logit_kernel(const int* __restrict__ sub, const int* __restrict__ obj,
                  const float* __restrict__ b_a1, const float* __restrict__ Wa2,
                  const float* __restrict__ b_a2) {
    const int e = blockIdx.x;
    const int tid = threadIdx.x;
    const int s = sub[e], o = obj[e];

    const float4* ra = (const float4*)(g_rel_att + (size_t)e * OD);
    const float4* bs = (const float4*)(g_box_att + (size_t)s * OD);
    const float4* bo = (const float4*)(g_box_att + (size_t)o * OD);
    const float4* bb = (const float4*)b_a1;
    const float4* w  = (const float4*)Wa2;

    float ps = 0.f, po = 0.f;
    for (int i = tid; i < OD / 4; i += blockDim.x) {
        float4 r = ra[i], b1 = bs[i], b2 = bo[i], bi = bb[i], wv = w[i];
        ps = fmaf(fmaxf(r.x + b1.x + bi.x, 0.f), wv.x, ps);
        ps = fmaf(fmaxf(r.y + b1.y + bi.y, 0.f), wv.y, ps);
        ps = fmaf(fmaxf(r.z + b1.z + bi.z, 0.f), wv.z, ps);
        ps = fmaf(fmaxf(r.w + b1.w + bi.w, 0.f), wv.w, ps);
        po = fmaf(fmaxf(r.x + b2.x + bi.x, 0.f), wv.x, po);
        po = fmaf(fmaxf(r.y + b2.y + bi.y, 0.f), wv.y, po);
        po = fmaf(fmaxf(r.z + b2.z + bi.z, 0.f), wv.z, po);
        po = fmaf(fmaxf(r.w + b2.w + bi.w, 0.f), wv.w, po);
    }
    __shared__ float red[2][8];
    #pragma unroll
    for (int off = 16; off > 0; off >>= 1) {
        ps += __shfl_down_sync(0xffffffffu, ps, off);
        po += __shfl_down_sync(0xffffffffu, po, off);
    }
    if ((tid & 31) == 0) { red[0][tid >> 5] = ps; red[1][tid >> 5] = po; }
    __syncthreads();
    if (tid == 0) {
        float a = 0.f, b = 0.f;
        #pragma unroll
        for (int wi = 0; wi < 8; wi++) { a += red[0][wi]; b += red[1][wi]; }
        float ba2 = b_a2[0];
        g_logit[e]      = a + ba2;
        g_logit[NE + e] = b + ba2;
    }
}

// ---------------- segment softmax ----------------
__device__ __forceinline__ void atomicMaxF(float* addr, float v) {
    if (v >= 0.f) atomicMax((int*)addr, __float_as_int(v));
    else          atomicMin((unsigned int*)addr, __float_as_uint(v));
}

__global__ void segmax_kernel(const int* __restrict__ sub, const int* __restrict__ obj) {
    int e = blockIdx.x * blockDim.x + threadIdx.x;
    if (e >= NE) return;
    atomicMaxF(&g_nmax[sub[e]], g_logit[e]);
    atomicMaxF(&g_nmax[NB + obj[e]], g_logit[NE + e]);
}

__global__ void expsum_kernel(const int* __restrict__ sub, const int* __restrict__ obj) {
    int e = blockIdx.x * blockDim.x + threadIdx.x;
    if (e >= NE) return;
    int s = sub[e], o = obj[e];
    float es = expf(g_logit[e] - g_nmax[s]);
    float eo = expf(g_logit[NE + e] - g_nmax[NB + o]);
    g_alpha[e] = es;
    g_alpha[NE + e] = eo;
    atomicAdd(&g_denom[s], es);
    atomicAdd(&g_denom[NB + o], eo);
}

__global__ void salpha_kernel() {
    int i = blockIdx.x * blockDim.x + threadIdx.x;
    if (i >= 2 * NB) return;
    float d = g_denom[i];
    g_salpha[i] = d / (d + 1e-9f);
}

// ---------------- weighted scatter ----------------
__global__ __launch_bounds__(256)
void scatter_kernel(const float* __restrict__ rel, const int* __restrict__ sub,
                    const int* __restrict__ obj) {
    const int e = blockIdx.x;
    const int tid = threadIdx.x;
    const int s = sub[e], o = obj[e];
    const float as = g_alpha[e] / (g_denom[s] + 1e-9f);
    const float ao = g_alpha[NE + e] / (g_denom[NB + o] + 1e-9f);

    const float4* r = (const float4*)(rel + (size_t)e * FD);
    float* ws = g_wsum + (size_t)s * FD;
    float* wo = g_wsum + ((size_t)NB + o) * FD;
    for (int i = tid; i < FD / 4; i += blockDim.x) {
        float4 v = r[i];
        int c = i * 4;
        atomicAdd(&ws[c + 0], as * v.x);
        atomicAdd(&ws[c + 1], as * v.y);
        atomicAdd(&ws[c + 2], as * v.z);
        atomicAdd(&ws[c + 3], as * v.w);
        atomicAdd(&wo[c + 0], ao * v.x);
        atomicAdd(&wo[c + 1], ao * v.y);
        atomicAdd(&wo[c + 2], ao * v.z);
        atomicAdd(&wo[c + 3], ao * v.w);
    }
}

// ---------------- acc init with biases ----------------
__global__ void biasinit_kernel(const float* __restrict__ b_box,
                                const float* __restrict__ b_sub,
                                const float* __restrict__ b_obj) {
    size_t idx = (size_t)blockIdx.x * blockDim.x + threadIdx.x;
    if (idx >= (size_t)NB * OD) return;
    int i = (int)(idx / OD);
    int n = (int)(idx % OD);
    g_acc[idx] = b_box[n] + g_salpha[i] * b_sub[n] + g_salpha[NB + i] * b_obj[n];
}

// ---------------- launch ----------------
static inline void split(const float* src, __nv_bfloat16* hi, __nv_bfloat16* lo, long n) {
    split_kernel<<<(int)((n / 4 + 255) / 256), 256>>>(src, hi, lo, n);
}
static inline void splith(const float* src, __nv_bfloat16* hi, long n) {
    splith_kernel<<<(int)((n / 4 + 255) / 256), 256>>>(src, hi, n);
}

extern "C" void kernel_launch(void* const* d_in, const int* in_sizes, int n_in,
                              void* d_out, int out_size) {
    const float* box_feats = (const float*)d_in[0];
    const float* rel_feats = (const float*)d_in[1];
    const int*   edge_sub  = (const int*)d_in[2];
    const int*   edge_obj  = (const int*)d_in[3];
    const float* W_box  = (const float*)d_in[4];
    const float* b_box  = (const float*)d_in[5];
    const float* W_sub  = (const float*)d_in[6];
    const float* b_sub  = (const float*)d_in[7];
    const float* W_obj  = (const float*)d_in[8];
    const float* b_obj  = (const float*)d_in[9];
    const float* Wa_box = (const float*)d_in[10];
    const float* Wa_rel = (const float*)d_in[11];
    const float* b_a1   = (const float*)d_in[12];
    const float* Wa2    = (const float*)d_in[13];
    const float* b_a2   = (const float*)d_in[14];
    float* out = (float*)d_out;

    float *box_att, *rel_att, *acc, *wsum;
    cudaGetSymbolAddress((void**)&box_att, g_box_att);
    cudaGetSymbolAddress((void**)&rel_att, g_rel_att);
    cudaGetSymbolAddress((void**)&acc, g_acc);
    cudaGetSymbolAddress((void**)&wsum, g_wsum);

    __nv_bfloat16 *relh, *boxh, *boxl, *wsh, *wsl;
    __nv_bfloat16 *Wabh, *Wabl, *Warh, *Wbh, *Wbl, *Wsh, *Wsl, *Woh, *Wol;
    cudaGetSymbolAddress((void**)&relh, g_relh);
    cudaGetSymbolAddress((void**)&boxh, g_boxh); cudaGetSymbolAddress((void**)&boxl, g_boxl);
    cudaGetSymbolAddress((void**)&wsh,  g_wsh);  cudaGetSymbolAddress((void**)&wsl,  g_wsl);
    cudaGetSymbolAddress((void**)&Wabh, g_Wabh); cudaGetSymbolAddress((void**)&Wabl, g_Wabl);
    cudaGetSymbolAddress((void**)&Warh, g_Warh);
    cudaGetSymbolAddress((void**)&Wbh,  g_Wbh);  cudaGetSymbolAddress((void**)&Wbl,  g_Wbl);
    cudaGetSymbolAddress((void**)&Wsh,  g_Wsh);  cudaGetSymbolAddress((void**)&Wsl,  g_Wsl);
    cudaGetSymbolAddress((void**)&Woh,  g_Woh);  cudaGetSymbolAddress((void**)&Wol,  g_Wol);

    init_kernel<<<2048, 256>>>();

    // splits: rel path (logits only) gets hi-only; value path gets exact hi/lo
    split(box_feats, boxh, boxl, (long)NB * OD);
    splith(rel_feats, relh, (long)NE * FD);
    split(Wa_box, Wabh, Wabl, (long)OD * OD);
    splith(Wa_rel, Warh, (long)FD * OD);
    split(W_box,  Wbh,  Wbl,  (long)OD * OD);
    split(W_sub,  Wsh,  Wsl,  (long)FD * OD);
    split(W_obj,  Woh,  Wol,  (long)FD * OD);

    // box_att = box_feats @ Wa_box   (3-product: shared with logit path, cheap insurance)
    mma_gemm<3><<<dim3(OD / 128, NB / 128), 256>>>(
        boxh, boxl, Wabh, Wabl, nullptr, box_att, NB, OD, OD, 0);
    // rel_att = rel_feats @ Wa_rel   (dominant; 1-product bf16 — logit path only)
    mma_gemm<1><<<dim3(OD / 128, NE / 128), 256>>>(
        relh, nullptr, Warh, nullptr, nullptr, rel_att, NE, OD, FD, 0);

    logit_kernel<<<NE, 256>>>(edge_sub, edge_obj, b_a1, Wa2, b_a2);
    segmax_kernel<<<(NE + 255) / 256, 256>>>(edge_sub, edge_obj);
    expsum_kernel<<<(NE + 255) / 256, 256>>>(edge_sub, edge_obj);
    salpha_kernel<<<(2 * NB + 255) / 256, 256>>>();
    scatter_kernel<<<NE, 256>>>(rel_feats, edge_sub, edge_obj);

    split(wsum, wsh, wsl, 2L * NB * FD);

    biasinit_kernel<<<(int)(((size_t)NB * OD + 255) / 256), 256>>>(b_box, b_sub, b_obj);

    // acc += box_feats @ W_box ; acc += wsum_s @ W_sub ; out = relu(acc + wsum_o @ W_obj)
    mma_gemm<3><<<dim3(OD / 128, NB / 128), 256>>>(
        boxh, boxl, Wbh, Wbl, acc, acc, NB, OD, OD, 0);
    mma_gemm<3><<<dim3(OD / 128, NB / 128), 256>>>(
        wsh, wsl, Wsh, Wsl, acc, acc, NB, OD, FD, 0);
    mma_gemm<3><<<dim3(OD / 128, NB / 128), 256>>>(
        wsh + (size_t)NB * FD, wsl + (size_t)NB * FD, Woh, Wol, acc, out,
        NB, OD, FD, 1);
}

// round 9
// speedup vs baseline: 1.4764x; 1.0073x over previous
#include <cuda_runtime.h>
#include <cuda_bf16.h>
#include <math.h>
#include <stdint.h>

#define NB 4096      // boxes
#define NE 32768     // edges
#define OD 2048      // obj_dim
#define FD 2432      // feats_dim

// ---------------- static scratch (no cudaMalloc allowed) ----------------
__device__ float g_box_att[(size_t)NB * OD];
__device__ float g_logit[2 * NE];
__device__ float g_alpha[2 * NE];
__device__ float g_nmax[2 * NB];
__device__ float g_denom[2 * NB];
__device__ float g_salpha[2 * NB];
__device__ float g_wsum[2ull * NB * FD];       // interleaved per node: [s-part FD | o-part FD]
__device__ float g_acc[(size_t)NB * OD];

// bf16 buffers
__device__ __nv_bfloat16 g_relh[(size_t)NE * FD];                    // hi only
__device__ __nv_bfloat16 g_boxh[(size_t)NB * OD], g_boxl[(size_t)NB * OD];
__device__ __nv_bfloat16 g_wsh[2ull * NB * FD],  g_wsl[2ull * NB * FD];
__device__ __nv_bfloat16 g_Wabh[(size_t)OD * OD], g_Wabl[(size_t)OD * OD];
__device__ __nv_bfloat16 g_Warh[(size_t)FD * OD];                    // hi only
__device__ __nv_bfloat16 g_Wbh[(size_t)OD * OD],  g_Wbl[(size_t)OD * OD];
__device__ __nv_bfloat16 g_Wch[2ull * FD * OD],  g_Wcl[2ull * FD * OD];  // [W_sub; W_obj]

// ---------------- init ----------------
__global__ void init_kernel(const float* __restrict__ b_a2) {
    size_t idx = (size_t)blockIdx.x * blockDim.x + threadIdx.x;
    size_t stride = (size_t)gridDim.x * blockDim.x;
    for (size_t i = idx; i < 2ull * NB * FD; i += stride) g_wsum[i] = 0.f;
    float ba2 = b_a2[0];
    for (size_t i = idx; i < 2 * NE; i += stride) g_logit[i] = ba2;
    for (size_t i = idx; i < 2 * NB; i += stride) {
        g_denom[i] = 0.f;
        g_nmax[i] = -INFINITY;
    }
}

// ---------------- fp32 -> bf16 hi/lo split ----------------
__global__ void split_kernel(const float* __restrict__ src,
                             __nv_bfloat16* __restrict__ hi,
                             __nv_bfloat16* __restrict__ lo, long n) {
    long i = ((long)blockIdx.x * blockDim.x + threadIdx.x) * 4;
    if (i >= n) return;
    float4 v = *(const float4*)(src + i);
    __nv_bfloat16 h[4], l[4];
    h[0] = __float2bfloat16_rn(v.x); l[0] = __float2bfloat16_rn(v.x - __bfloat162float(h[0]));
    h[1] = __float2bfloat16_rn(v.y); l[1] = __float2bfloat16_rn(v.y - __bfloat162float(h[1]));
    h[2] = __float2bfloat16_rn(v.z); l[2] = __float2bfloat16_rn(v.z - __bfloat162float(h[2]));
    h[3] = __float2bfloat16_rn(v.w); l[3] = __float2bfloat16_rn(v.w - __bfloat162float(h[3]));
    *(uint2*)(hi + i) = *(uint2*)h;
    *(uint2*)(lo + i) = *(uint2*)l;
}

__global__ void splith_kernel(const float* __restrict__ src,
                              __nv_bfloat16* __restrict__ hi, long n) {
    long i = ((long)blockIdx.x * blockDim.x + threadIdx.x) * 4;
    if (i >= n) return;
    float4 v = *(const float4*)(src + i);
    __nv_bfloat16 h[4];
    h[0] = __float2bfloat16_rn(v.x);
    h[1] = __float2bfloat16_rn(v.y);
    h[2] = __float2bfloat16_rn(v.z);
    h[3] = __float2bfloat16_rn(v.w);
    *(uint2*)(hi + i) = *(uint2*)h;
}

// ---------------- MMA helpers ----------------
__device__ __forceinline__ uint32_t sptr(const void* p) {
    return (uint32_t)__cvta_generic_to_shared(p);
}
__device__ __forceinline__ void ldm4(uint32_t* r, uint32_t a) {
    asm volatile("ldmatrix.sync.aligned.m8n8.x4.shared.b16 {%0,%1,%2,%3}, [%4];"
        : "=r"(r[0]), "=r"(r[1]), "=r"(r[2]), "=r"(r[3]) : "r"(a));
}
__device__ __forceinline__ void ldm4t(uint32_t* r, uint32_t a) {
    asm volatile("ldmatrix.sync.aligned.m8n8.x4.trans.shared.b16 {%0,%1,%2,%3}, [%4];"
        : "=r"(r[0]), "=r"(r[1]), "=r"(r[2]), "=r"(r[3]) : "r"(a));
}
__device__ __forceinline__ void mma16816(float* c, const uint32_t* a, const uint32_t* b) {
    asm volatile("mma.sync.aligned.m16n8k16.row.col.f32.bf16.bf16.f32 "
        "{%0,%1,%2,%3}, {%4,%5,%6,%7}, {%8,%9}, {%0,%1,%2,%3};"
        : "+f"(c[0]), "+f"(c[1]), "+f"(c[2]), "+f"(c[3])
        : "r"(a[0]), "r"(a[1]), "r"(a[2]), "r"(a[3]), "r"(b[0]), "r"(b[1]));
}

// ---------------- generic 3-product hi/lo GEMM (round-4 proven) ----------------
#define LDA 40
#define LDB 136

__global__ __launch_bounds__(256, 2)
void mma_gemm3(const __nv_bfloat16* __restrict__ Ah, const __nv_bfloat16* __restrict__ Al,
               const __nv_bfloat16* __restrict__ Bh, const __nv_bfloat16* __restrict__ Bl,
               const float* __restrict__ Cin, float* __restrict__ Cout,
               int M, int N, int K, int do_relu) {
    __shared__ __nv_bfloat16 sAh[128 * LDA], sAl[128 * LDA];
    __shared__ __nv_bfloat16 sBh[32 * LDB],  sBl[32 * LDB];

    const int tid  = threadIdx.x;
    const int lane = tid & 31;
    const int wid  = tid >> 5;
    const int wm   = wid & 1;
    const int wn   = wid >> 1;
    const int bm   = blockIdx.y * 128;
    const int bn   = blockIdx.x * 128;

    float acc[4][4][4];
    #pragma unroll
    for (int i = 0; i < 4; i++)
        #pragma unroll
        for (int j = 0; j < 4; j++)
            #pragma unroll
            for (int q = 0; q < 4; q++) acc[i][j][q] = 0.f;

    for (int k0 = 0; k0 < K; k0 += 32) {
        #pragma unroll
        for (int p = 0; p < 2; p++) {
            int u  = tid + p * 256;
            int r  = u >> 2,  cg = (u & 3) << 3;
            int rb = u >> 4,  cb = (u & 15) << 3;
            *(uint4*)&sAh[r * LDA + cg]  = *(const uint4*)(Ah + (size_t)(bm + r) * K + k0 + cg);
            *(uint4*)&sAl[r * LDA + cg]  = *(const uint4*)(Al + (size_t)(bm + r) * K + k0 + cg);
            *(uint4*)&sBh[rb * LDB + cb] = *(const uint4*)(Bh + (size_t)(k0 + rb) * N + bn + cb);
            *(uint4*)&sBl[rb * LDB + cb] = *(const uint4*)(Bl + (size_t)(k0 + rb) * N + bn + cb);
        }
        __syncthreads();

        #pragma unroll
        for (int ks = 0; ks < 32; ks += 16) {
            uint32_t bh[2][4], bl[2][4];
            #pragma unroll
            for (int nh = 0; nh < 2; nh++) {
                int rr = ks + (lane & 15);
                int cc = wn * 32 + nh * 16 + ((lane >> 4) << 3);
                ldm4t(bh[nh], sptr(&sBh[rr * LDB + cc]));
                ldm4t(bl[nh], sptr(&sBl[rr * LDB + cc]));
            }
            #pragma unroll
            for (int mt = 0; mt < 4; mt++) {
                uint32_t ah[4], al[4];
                int ar = wm * 64 + mt * 16 + (lane & 15);
                int ac = ks + ((lane >> 4) << 3);
                ldm4(ah, sptr(&sAh[ar * LDA + ac]));
                ldm4(al, sptr(&sAl[ar * LDA + ac]));
                #pragma unroll
                for (int nt = 0; nt < 4; nt++) {
                    const uint32_t* ph = &bh[nt >> 1][(nt & 1) * 2];
                    const uint32_t* pl = &bl[nt >> 1][(nt & 1) * 2];
                    mma16816(acc[mt][nt], ah, ph);
                    mma16816(acc[mt][nt], ah, pl);
                    mma16816(acc[mt][nt], al, ph);
                }
            }
        }
        __syncthreads();
    }

    const int r0 = bm + wm * 64;
    const int c0 = bn + wn * 32;
    #pragma unroll
    for (int mt = 0; mt < 4; mt++) {
        #pragma unroll
        for (int nt = 0; nt < 4; nt++) {
            int row = r0 + mt * 16 + (lane >> 2);
            int col = c0 + nt * 8 + ((lane & 3) << 1);
            float2 v01 = make_float2(acc[mt][nt][0], acc[mt][nt][1]);
            float2 v23 = make_float2(acc[mt][nt][2], acc[mt][nt][3]);
            if (Cin) {
                float2 c1 = *(const float2*)(Cin + (size_t)row * N + col);
                float2 c2 = *(const float2*)(Cin + (size_t)(row + 8) * N + col);
                v01.x += c1.x; v01.y += c1.y;
                v23.x += c2.x; v23.y += c2.y;
            }
            if (do_relu) {
                v01.x = fmaxf(v01.x, 0.f); v01.y = fmaxf(v01.y, 0.f);
                v23.x = fmaxf(v23.x, 0.f); v23.y = fmaxf(v23.y, 0.f);
            }
            *(float2*)(Cout + (size_t)row * N + col)       = v01;
            *(float2*)(Cout + (size_t)(row + 8) * N + col) = v23;
        }
    }
}

// ---------------- rel GEMM with fused logit epilogue ----------------
// Computes partial logits directly from the 128x256 rel_att tile in registers:
//   g_logit[e]    += sum_c relu(rel[e][c] + box_att[sub[e]][c] + b_a1[c]) * Wa2[c]
//   g_logit[NE+e] += ... obj ...
// rel_att is never written to memory.
#define RLDB 264

__global__ __launch_bounds__(512, 1)
void rel_logit_gemm(const __nv_bfloat16* __restrict__ Ah,
                    const __nv_bfloat16* __restrict__ Bh,
                    const int* __restrict__ sub, const int* __restrict__ obj,
                    const float* __restrict__ b_a1, const float* __restrict__ Wa2,
                    int M, int N, int K) {
    __shared__ __nv_bfloat16 sA[128 * LDA];
    __shared__ __nv_bfloat16 sB[32 * RLDB];

    const int tid  = threadIdx.x;
    const int lane = tid & 31;
    const int wid  = tid >> 5;
    const int wm   = wid & 3;       // 4 x 32-row slabs
    const int wn   = wid >> 2;      // 4 x 64-col slabs
    const int bm   = blockIdx.y * 128;
    const int bn   = blockIdx.x * 256;

    float acc[2][8][4];
    #pragma unroll
    for (int i = 0; i < 2; i++)
        #pragma unroll
        for (int j = 0; j < 8; j++)
            #pragma unroll
            for (int q = 0; q < 4; q++) acc[i][j][q] = 0.f;

    for (int k0 = 0; k0 < K; k0 += 32) {
        {
            int r = tid >> 2, cg = (tid & 3) << 3;       // A: 128x32, 1 vec/thread
            *(uint4*)&sA[r * LDA + cg] = *(const uint4*)(Ah + (size_t)(bm + r) * K + k0 + cg);
            #pragma unroll
            for (int p = 0; p < 2; p++) {                // B: 32x256, 2 vec/thread
                int u = tid + (p << 9);
                int rb = u >> 5, cb = (u & 31) << 3;
                *(uint4*)&sB[rb * RLDB + cb] = *(const uint4*)(Bh + (size_t)(k0 + rb) * N + bn + cb);
            }
        }
        __syncthreads();

        #pragma unroll
        for (int ks = 0; ks < 32; ks += 16) {
            uint32_t bfr[4][4];
            #pragma unroll
            for (int nh = 0; nh < 4; nh++) {
                int rr = ks + (lane & 15);
                int cc = wn * 64 + nh * 16 + ((lane >> 4) << 3);
                ldm4t(bfr[nh], sptr(&sB[rr * RLDB + cc]));
            }
            #pragma unroll
            for (int mt = 0; mt < 2; mt++) {
                uint32_t a[4];
                int ar = wm * 32 + mt * 16 + (lane & 15);
                int ac = ks + ((lane >> 4) << 3);
                ldm4(a, sptr(&sA[ar * LDA + ac]));
                #pragma unroll
                for (int nt = 0; nt < 8; nt++)
                    mma16816(acc[mt][nt], a, &bfr[nt >> 1][(nt & 1) * 2]);
            }
        }
        __syncthreads();
    }

    // fused logit epilogue
    float ps[4] = {0.f, 0.f, 0.f, 0.f}, po[4] = {0.f, 0.f, 0.f, 0.f};
    int rows[4], si[4], oi[4];
    #pragma unroll
    for (int i = 0; i < 4; i++) {
        int mt = i >> 1, h = i & 1;
        rows[i] = bm + wm * 32 + mt * 16 + (lane >> 2) + h * 8;
        si[i] = sub[rows[i]];
        oi[i] = obj[rows[i]];
    }
    #pragma unroll
    for (int nt = 0; nt < 8; nt++) {
        int c = bn + wn * 64 + nt * 8 + ((lane & 3) << 1);
        float2 wv = *(const float2*)(Wa2 + c);
        float2 bv = *(const float2*)(b_a1 + c);
        #pragma unroll
        for (int i = 0; i < 4; i++) {
            int mt = i >> 1, h = i & 1;
            float a0 = acc[mt][nt][h * 2 + 0];
            float a1 = acc[mt][nt][h * 2 + 1];
            float2 bsv = *(const float2*)(g_box_att + (size_t)si[i] * OD + c);
            float2 bov = *(const float2*)(g_box_att + (size_t)oi[i] * OD + c);
            ps[i] = fmaf(fmaxf(a0 + bsv.x + bv.x, 0.f), wv.x, ps[i]);
            ps[i] = fmaf(fmaxf(a1 + bsv.y + bv.y, 0.f), wv.y, ps[i]);
            po[i] = fmaf(fmaxf(a0 + bov.x + bv.x, 0.f), wv.x, po[i]);
            po[i] = fmaf(fmaxf(a1 + bov.y + bv.y, 0.f), wv.y, po[i]);
        }
    }
    #pragma unroll
    for (int i = 0; i < 4; i++) {
        ps[i] += __shfl_xor_sync(0xffffffffu, ps[i], 1);
        ps[i] += __shfl_xor_sync(0xffffffffu, ps[i], 2);
        po[i] += __shfl_xor_sync(0xffffffffu, po[i], 1);
        po[i] += __shfl_xor_sync(0xffffffffu, po[i], 2);
        if ((lane & 3) == 0) {
            atomicAdd(&g_logit[rows[i]], ps[i]);
            atomicAdd(&g_logit[NE + rows[i]], po[i]);
        }
    }
}

// ---------------- segment softmax ----------------
__device__ __forceinline__ void atomicMaxF(float* addr, float v) {
    if (v >= 0.f) atomicMax((int*)addr, __float_as_int(v));
    else          atomicMin((unsigned int*)addr, __float_as_uint(v));
}

__global__ void segmax_kernel(const int* __restrict__ sub, const int* __restrict__ obj) {
    int e = blockIdx.x * blockDim.x + threadIdx.x;
    if (e >= NE) return;
    atomicMaxF(&g_nmax[sub[e]], g_logit[e]);
    atomicMaxF(&g_nmax[NB + obj[e]], g_logit[NE + e]);
}

__global__ void expsum_kernel(const int* __restrict__ sub, const int* __restrict__ obj) {
    int e = blockIdx.x * blockDim.x + threadIdx.x;
    if (e >= NE) return;
    int s = sub[e], o = obj[e];
    float es = expf(g_logit[e] - g_nmax[s]);
    float eo = expf(g_logit[NE + e] - g_nmax[NB + o]);
    g_alpha[e] = es;
    g_alpha[NE + e] = eo;
    atomicAdd(&g_denom[s], es);
    atomicAdd(&g_denom[NB + o], eo);
}

__global__ void salpha_kernel() {
    int i = blockIdx.x * blockDim.x + threadIdx.x;
    if (i >= 2 * NB) return;
    float d = g_denom[i];
    g_salpha[i] = d / (d + 1e-9f);
}

// ---------------- weighted scatter (interleaved wsum layout) ----------------
__global__ __launch_bounds__(256)
void scatter_kernel(const float* __restrict__ rel, const int* __restrict__ sub,
                    const int* __restrict__ obj) {
    const int e = blockIdx.x;
    const int tid = threadIdx.x;
    const int s = sub[e], o = obj[e];
    const float as = g_alpha[e] / (g_denom[s] + 1e-9f);
    const float ao = g_alpha[NE + e] / (g_denom[NB + o] + 1e-9f);

    const float4* r = (const float4*)(rel + (size_t)e * FD);
    float* ws = g_wsum + (size_t)s * (2 * FD);        // s-part at node row offset 0
    float* wo = g_wsum + (size_t)o * (2 * FD) + FD;   // o-part at offset FD
    for (int i = tid; i < FD / 4; i += blockDim.x) {
        float4 v = r[i];
        int c = i * 4;
        atomicAdd(&ws[c + 0], as * v.x);
        atomicAdd(&ws[c + 1], as * v.y);
        atomicAdd(&ws[c + 2], as * v.z);
        atomicAdd(&ws[c + 3], as * v.w);
        atomicAdd(&wo[c + 0], ao * v.x);
        atomicAdd(&wo[c + 1], ao * v.y);
        atomicAdd(&wo[c + 2], ao * v.z);
        atomicAdd(&wo[c + 3], ao * v.w);
    }
}

// ---------------- acc init with biases ----------------
__global__ void biasinit_kernel(const float* __restrict__ b_box,
                                const float* __restrict__ b_sub,
                                const float* __restrict__ b_obj) {
    size_t idx = (size_t)blockIdx.x * blockDim.x + threadIdx.x;
    if (idx >= (size_t)NB * OD) return;
    int i = (int)(idx / OD);
    int n = (int)(idx % OD);
    g_acc[idx] = b_box[n] + g_salpha[i] * b_sub[n] + g_salpha[NB + i] * b_obj[n];
}

// ---------------- launch ----------------
static inline void split(const float* src, __nv_bfloat16* hi, __nv_bfloat16* lo, long n) {
    split_kernel<<<(int)((n / 4 + 255) / 256), 256>>>(src, hi, lo, n);
}
static inline void splith(const float* src, __nv_bfloat16* hi, long n) {
    splith_kernel<<<(int)((n / 4 + 255) / 256), 256>>>(src, hi, n);
}

extern "C" void kernel_launch(void* const* d_in, const int* in_sizes, int n_in,
                              void* d_out, int out_size) {
    const float* box_feats = (const float*)d_in[0];
    const float* rel_feats = (const float*)d_in[1];
    const int*   edge_sub  = (const int*)d_in[2];
    const int*   edge_obj  = (const int*)d_in[3];
    const float* W_box  = (const float*)d_in[4];
    const float* b_box  = (const float*)d_in[5];
    const float* W_sub  = (const float*)d_in[6];
    const float* b_sub  = (const float*)d_in[7];
    const float* W_obj  = (const float*)d_in[8];
    const float* b_obj  = (const float*)d_in[9];
    const float* Wa_box = (const float*)d_in[10];
    const float* Wa_rel = (const float*)d_in[11];
    const float* b_a1   = (const float*)d_in[12];
    const float* Wa2    = (const float*)d_in[13];
    const float* b_a2   = (const float*)d_in[14];
    float* out = (float*)d_out;

    float *box_att, *acc, *wsum;
    cudaGetSymbolAddress((void**)&box_att, g_box_att);
    cudaGetSymbolAddress((void**)&acc, g_acc);
    cudaGetSymbolAddress((void**)&wsum, g_wsum);

    __nv_bfloat16 *relh, *boxh, *boxl, *wsh, *wsl;
    __nv_bfloat16 *Wabh, *Wabl, *Warh, *Wbh, *Wbl, *Wch, *Wcl;
    cudaGetSymbolAddress((void**)&relh, g_relh);
    cudaGetSymbolAddress((void**)&boxh, g_boxh); cudaGetSymbolAddress((void**)&boxl, g_boxl);
    cudaGetSymbolAddress((void**)&wsh,  g_wsh);  cudaGetSymbolAddress((void**)&wsl,  g_wsl);
    cudaGetSymbolAddress((void**)&Wabh, g_Wabh); cudaGetSymbolAddress((void**)&Wabl, g_Wabl);
    cudaGetSymbolAddress((void**)&Warh, g_Warh);
    cudaGetSymbolAddress((void**)&Wbh,  g_Wbh);  cudaGetSymbolAddress((void**)&Wbl,  g_Wbl);
    cudaGetSymbolAddress((void**)&Wch,  g_Wch);  cudaGetSymbolAddress((void**)&Wcl,  g_Wcl);

    init_kernel<<<2048, 256>>>(b_a2);

    // splits
    split(box_feats, boxh, boxl, (long)NB * OD);
    splith(rel_feats, relh, (long)NE * FD);
    split(Wa_box, Wabh, Wabl, (long)OD * OD);
    splith(Wa_rel, Warh, (long)FD * OD);
    split(W_box,  Wbh,  Wbl,  (long)OD * OD);
    split(W_sub,  Wch,  Wcl,  (long)FD * OD);                          // rows 0..FD-1
    split(W_obj,  Wch + (size_t)FD * OD, Wcl + (size_t)FD * OD, (long)FD * OD);  // rows FD..2FD-1

    // box_att = box_feats @ Wa_box   (3-product exact)
    mma_gemm3<<<dim3(OD / 128, NB / 128), 256>>>(
        boxh, boxl, Wabh, Wabl, nullptr, box_att, NB, OD, OD, 0);

    // fused: logits += partial dot over relu(rel@Wa_rel + box_att[idx] + b_a1) . Wa2
    rel_logit_gemm<<<dim3(OD / 256, NE / 128), 512>>>(
        relh, Warh, edge_sub, edge_obj, b_a1, Wa2, NE, OD, FD);

    segmax_kernel<<<(NE + 255) / 256, 256>>>(edge_sub, edge_obj);
    expsum_kernel<<<(NE + 255) / 256, 256>>>(edge_sub, edge_obj);
    salpha_kernel<<<(2 * NB + 255) / 256, 256>>>();
    scatter_kernel<<<NE, 256>>>(rel_feats, edge_sub, edge_obj);

    split(wsum, wsh, wsl, 2L * NB * FD);

    biasinit_kernel<<<(int)(((size_t)NB * OD + 255) / 256), 256>>>(b_box, b_sub, b_obj);

    // acc += box_feats @ W_box ; out = relu(acc + wsum_cat @ [W_sub; W_obj])
    mma_gemm3<<<dim3(OD / 128, NB / 128), 256>>>(
        boxh, boxl, Wbh, Wbl, acc, acc, NB, OD, OD, 0);
    mma_gemm3<<<dim3(OD / 128, NB / 128), 256>>>(
        wsh, wsl, Wch, Wcl, acc, out, NB, OD, 2 * FD, 1);
}

// round 10
// speedup vs baseline: 1.6600x; 1.1243x over previous
#include <cuda_runtime.h>
#include <cuda_fp16.h>
#include <math.h>
#include <stdint.h>

#define NB 4096      // boxes
#define NE 32768     // edges
#define OD 2048      // obj_dim
#define FD 2432      // feats_dim

// ---------------- static scratch (no cudaMalloc allowed) ----------------
__device__ float g_box_att[(size_t)NB * OD];
__device__ float g_logit[2 * NE];
__device__ float g_alpha[2 * NE];
__device__ float g_nmax[2 * NB];
__device__ float g_denom[2 * NB];
__device__ float g_salpha[2 * NB];
__device__ float g_wsum[2ull * NB * FD];       // interleaved per node: [s FD | o FD]
__device__ float g_acc[(size_t)NB * OD];

// fp16 buffers
__device__ __half g_relh[(size_t)NE * FD];                     // hi only
__device__ __half g_boxh[(size_t)NB * OD], g_boxl[(size_t)NB * OD];
__device__ __half g_wsh[2ull * NB * FD],  g_wsl[2ull * NB * FD];
__device__ __half g_Wabh[(size_t)OD * OD];                     // hi only (logit path)
__device__ __half g_Warh[(size_t)FD * OD];                     // hi only
__device__ __half g_Wbh[(size_t)OD * OD];                      // hi only (2-product B)
__device__ __half g_Wch[2ull * FD * OD];                       // [W_sub; W_obj] hi only

// ---------------- init ----------------
__global__ void init_kernel(const float* __restrict__ b_a2) {
    size_t idx = (size_t)blockIdx.x * blockDim.x + threadIdx.x;
    size_t stride = (size_t)gridDim.x * blockDim.x;
    for (size_t i = idx; i < 2ull * NB * FD; i += stride) g_wsum[i] = 0.f;
    float ba2 = b_a2[0];
    for (size_t i = idx; i < 2 * NE; i += stride) g_logit[i] = ba2;
    for (size_t i = idx; i < 2 * NB; i += stride) {
        g_denom[i] = 0.f;
        g_nmax[i] = -INFINITY;
    }
}

// ---------------- fp32 -> fp16 hi/lo split ----------------
__global__ void split_kernel(const float* __restrict__ src,
                             __half* __restrict__ hi,
                             __half* __restrict__ lo, long n) {
    long i = ((long)blockIdx.x * blockDim.x + threadIdx.x) * 4;
    if (i >= n) return;
    float4 v = *(const float4*)(src + i);
    __half h[4], l[4];
    h[0] = __float2half_rn(v.x); l[0] = __float2half_rn(v.x - __half2float(h[0]));
    h[1] = __float2half_rn(v.y); l[1] = __float2half_rn(v.y - __half2float(h[1]));
    h[2] = __float2half_rn(v.z); l[2] = __float2half_rn(v.z - __half2float(h[2]));
    h[3] = __float2half_rn(v.w); l[3] = __float2half_rn(v.w - __half2float(h[3]));
    *(uint2*)(hi + i) = *(uint2*)h;
    *(uint2*)(lo + i) = *(uint2*)l;
}

__global__ void splith_kernel(const float* __restrict__ src,
                              __half* __restrict__ hi, long n) {
    long i = ((long)blockIdx.x * blockDim.x + threadIdx.x) * 4;
    if (i >= n) return;
    float4 v = *(const float4*)(src + i);
    __half h[4];
    h[0] = __float2half_rn(v.x);
    h[1] = __float2half_rn(v.y);
    h[2] = __float2half_rn(v.z);
    h[3] = __float2half_rn(v.w);
    *(uint2*)(hi + i) = *(uint2*)h;
}

// ---------------- MMA helpers ----------------
__device__ __forceinline__ uint32_t sptr(const void* p) {
    return (uint32_t)__cvta_generic_to_shared(p);
}
__device__ __forceinline__ void ldm4(uint32_t* r, uint32_t a) {
    asm volatile("ldmatrix.sync.aligned.m8n8.x4.shared.b16 {%0,%1,%2,%3}, [%4];"
        : "=r"(r[0]), "=r"(r[1]), "=r"(r[2]), "=r"(r[3]) : "r"(a));
}
__device__ __forceinline__ void ldm4t(uint32_t* r, uint32_t a) {
    asm volatile("ldmatrix.sync.aligned.m8n8.x4.trans.shared.b16 {%0,%1,%2,%3}, [%4];"
        : "=r"(r[0]), "=r"(r[1]), "=r"(r[2]), "=r"(r[3]) : "r"(a));
}
__device__ __forceinline__ void mma16816(float* c, const uint32_t* a, const uint32_t* b) {
    asm volatile("mma.sync.aligned.m16n8k16.row.col.f32.f16.f16.f32 "
        "{%0,%1,%2,%3}, {%4,%5,%6,%7}, {%8,%9}, {%0,%1,%2,%3};"
        : "+f"(c[0]), "+f"(c[1]), "+f"(c[2]), "+f"(c[3])
        : "r"(a[0]), "r"(a[1]), "r"(a[2]), "r"(a[3]), "r"(b[0]), "r"(b[1]));
}

// ---------------- fp16 GEMM (NPROD=1: Ah@Bh ; NPROD=2: (Ah+Al)@Bh) ----------------
// CTA tile 128x128, BK=32, 8 warps (2x4), warp tile 64x32.
#define LDA 40
#define LDB 136

template <int NPROD>
__global__ __launch_bounds__(256, 2)
void mma_gemm(const __half* __restrict__ Ah, const __half* __restrict__ Al,
              const __half* __restrict__ Bh,
              const float* __restrict__ Cin, float* __restrict__ Cout,
              int M, int N, int K, int do_relu) {
    __shared__ __half sAh[128 * LDA], sAl[NPROD == 2 ? 128 * LDA : 1];
    __shared__ __half sBh[32 * LDB];

    const int tid  = threadIdx.x;
    const int lane = tid & 31;
    const int wid  = tid >> 5;
    const int wm   = wid & 1;
    const int wn   = wid >> 1;
    const int bm   = blockIdx.y * 128;
    const int bn   = blockIdx.x * 128;

    float acc[4][4][4];
    #pragma unroll
    for (int i = 0; i < 4; i++)
        #pragma unroll
        for (int j = 0; j < 4; j++)
            #pragma unroll
            for (int q = 0; q < 4; q++) acc[i][j][q] = 0.f;

    for (int k0 = 0; k0 < K; k0 += 32) {
        #pragma unroll
        for (int p = 0; p < 2; p++) {
            int u  = tid + p * 256;
            int r  = u >> 2,  cg = (u & 3) << 3;
            int rb = u >> 4,  cb = (u & 15) << 3;
            *(uint4*)&sAh[r * LDA + cg]  = *(const uint4*)(Ah + (size_t)(bm + r) * K + k0 + cg);
            if (NPROD == 2)
                *(uint4*)&sAl[r * LDA + cg] = *(const uint4*)(Al + (size_t)(bm + r) * K + k0 + cg);
            *(uint4*)&sBh[rb * LDB + cb] = *(const uint4*)(Bh + (size_t)(k0 + rb) * N + bn + cb);
        }
        __syncthreads();

        #pragma unroll
        for (int ks = 0; ks < 32; ks += 16) {
            uint32_t bh[2][4];
            #pragma unroll
            for (int nh = 0; nh < 2; nh++) {
                int rr = ks + (lane & 15);
                int cc = wn * 32 + nh * 16 + ((lane >> 4) << 3);
                ldm4t(bh[nh], sptr(&sBh[rr * LDB + cc]));
            }
            #pragma unroll
            for (int mt = 0; mt < 4; mt++) {
                uint32_t ah[4], al[4];
                int ar = wm * 64 + mt * 16 + (lane & 15);
                int ac = ks + ((lane >> 4) << 3);
                ldm4(ah, sptr(&sAh[ar * LDA + ac]));
                if (NPROD == 2) ldm4(al, sptr(&sAl[ar * LDA + ac]));
                #pragma unroll
                for (int nt = 0; nt < 4; nt++) {
                    const uint32_t* ph = &bh[nt >> 1][(nt & 1) * 2];
                    mma16816(acc[mt][nt], ah, ph);
                    if (NPROD == 2) mma16816(acc[mt][nt], al, ph);
                }
            }
        }
        __syncthreads();
    }

    const int r0 = bm + wm * 64;
    const int c0 = bn + wn * 32;
    #pragma unroll
    for (int mt = 0; mt < 4; mt++) {
        #pragma unroll
        for (int nt = 0; nt < 4; nt++) {
            int row = r0 + mt * 16 + (lane >> 2);
            int col = c0 + nt * 8 + ((lane & 3) << 1);
            float2 v01 = make_float2(acc[mt][nt][0], acc[mt][nt][1]);
            float2 v23 = make_float2(acc[mt][nt][2], acc[mt][nt][3]);
            if (Cin) {
                float2 c1 = *(const float2*)(Cin + (size_t)row * N + col);
                float2 c2 = *(const float2*)(Cin + (size_t)(row + 8) * N + col);
                v01.x += c1.x; v01.y += c1.y;
                v23.x += c2.x; v23.y += c2.y;
            }
            if (do_relu) {
                v01.x = fmaxf(v01.x, 0.f); v01.y = fmaxf(v01.y, 0.f);
                v23.x = fmaxf(v23.x, 0.f); v23.y = fmaxf(v23.y, 0.f);
            }
            *(float2*)(Cout + (size_t)row * N + col)       = v01;
            *(float2*)(Cout + (size_t)(row + 8) * N + col) = v23;
        }
    }
}

// ---------------- rel GEMM with fused logit epilogue (fp16, proven round-9) ----
#define RLDB 264

__global__ __launch_bounds__(512, 1)
void rel_logit_gemm(const __half* __restrict__ Ah,
                    const __half* __restrict__ Bh,
                    const int* __restrict__ sub, const int* __restrict__ obj,
                    const float* __restrict__ b_a1, const float* __restrict__ Wa2,
                    int M, int N, int K) {
    __shared__ __half sA[128 * LDA];
    __shared__ __half sB[32 * RLDB];

    const int tid  = threadIdx.x;
    const int lane = tid & 31;
    const int wid  = tid >> 5;
    const int wm   = wid & 3;       // 4 x 32-row slabs
    const int wn   = wid >> 2;      // 4 x 64-col slabs
    const int bm   = blockIdx.y * 128;
    const int bn   = blockIdx.x * 256;

    float acc[2][8][4];
    #pragma unroll
    for (int i = 0; i < 2; i++)
        #pragma unroll
        for (int j = 0; j < 8; j++)
            #pragma unroll
            for (int q = 0; q < 4; q++) acc[i][j][q] = 0.f;

    for (int k0 = 0; k0 < K; k0 += 32) {
        {
            int r = tid >> 2, cg = (tid & 3) << 3;
            *(uint4*)&sA[r * LDA + cg] = *(const uint4*)(Ah + (size_t)(bm + r) * K + k0 + cg);
            #pragma unroll
            for (int p = 0; p < 2; p++) {
                int u = tid + (p << 9);
                int rb = u >> 5, cb = (u & 31) << 3;
                *(uint4*)&sB[rb * RLDB + cb] = *(const uint4*)(Bh + (size_t)(k0 + rb) * N + bn + cb);
            }
        }
        __syncthreads();

        #pragma unroll
        for (int ks = 0; ks < 32; ks += 16) {
            uint32_t bfr[4][4];
            #pragma unroll
            for (int nh = 0; nh < 4; nh++) {
                int rr = ks + (lane & 15);
                int cc = wn * 64 + nh * 16 + ((lane >> 4) << 3);
                ldm4t(bfr[nh], sptr(&sB[rr * RLDB + cc]));
            }
            #pragma unroll
            for (int mt = 0; mt < 2; mt++) {
                uint32_t a[4];
                int ar = wm * 32 + mt * 16 + (lane & 15);
                int ac = ks + ((lane >> 4) << 3);
                ldm4(a, sptr(&sA[ar * LDA + ac]));
                #pragma unroll
                for (int nt = 0; nt < 8; nt++)
                    mma16816(acc[mt][nt], a, &bfr[nt >> 1][(nt & 1) * 2]);
            }
        }
        __syncthreads();
    }

    // fused logit epilogue
    float ps[4] = {0.f, 0.f, 0.f, 0.f}, po[4] = {0.f, 0.f, 0.f, 0.f};
    int rows[4], si[4], oi[4];
    #pragma unroll
    for (int i = 0; i < 4; i++) {
        int mt = i >> 1, h = i & 1;
        rows[i] = bm + wm * 32 + mt * 16 + (lane >> 2) + h * 8;
        si[i] = sub[rows[i]];
        oi[i] = obj[rows[i]];
    }
    #pragma unroll
    for (int nt = 0; nt < 8; nt++) {
        int c = bn + wn * 64 + nt * 8 + ((lane & 3) << 1);
        float2 wv = *(const float2*)(Wa2 + c);
        float2 bv = *(const float2*)(b_a1 + c);
        #pragma unroll
        for (int i = 0; i < 4; i++) {
            int mt = i >> 1, h = i & 1;
            float a0 = acc[mt][nt][h * 2 + 0];
            float a1 = acc[mt][nt][h * 2 + 1];
            float2 bsv = *(const float2*)(g_box_att + (size_t)si[i] * OD + c);
            float2 bov = *(const float2*)(g_box_att + (size_t)oi[i] * OD + c);
            ps[i] = fmaf(fmaxf(a0 + bsv.x + bv.x, 0.f), wv.x, ps[i]);
            ps[i] = fmaf(fmaxf(a1 + bsv.y + bv.y, 0.f), wv.y, ps[i]);
            po[i] = fmaf(fmaxf(a0 + bov.x + bv.x, 0.f), wv.x, po[i]);
            po[i] = fmaf(fmaxf(a1 + bov.y + bv.y, 0.f), wv.y, po[i]);
        }
    }
    #pragma unroll
    for (int i = 0; i < 4; i++) {
        ps[i] += __shfl_xor_sync(0xffffffffu, ps[i], 1);
        ps[i] += __shfl_xor_sync(0xffffffffu, ps[i], 2);
        po[i] += __shfl_xor_sync(0xffffffffu, po[i], 1);
        po[i] += __shfl_xor_sync(0xffffffffu, po[i], 2);
        if ((lane & 3) == 0) {
            atomicAdd(&g_logit[rows[i]], ps[i]);
            atomicAdd(&g_logit[NE + rows[i]], po[i]);
        }
    }
}

// ---------------- segment softmax ----------------
__device__ __forceinline__ void atomicMaxF(float* addr, float v) {
    if (v >= 0.f) atomicMax((int*)addr, __float_as_int(v));
    else          atomicMin((unsigned int*)addr, __float_as_uint(v));
}

__global__ void segmax_kernel(const int* __restrict__ sub, const int* __restrict__ obj) {
    int e = blockIdx.x * blockDim.x + threadIdx.x;
    if (e >= NE) return;
    atomicMaxF(&g_nmax[sub[e]], g_logit[e]);
    atomicMaxF(&g_nmax[NB + obj[e]], g_logit[NE + e]);
}

__global__ void expsum_kernel(const int* __restrict__ sub, const int* __restrict__ obj) {
    int e = blockIdx.x * blockDim.x + threadIdx.x;
    if (e >= NE) return;
    int s = sub[e], o = obj[e];
    float es = expf(g_logit[e] - g_nmax[s]);
    float eo = expf(g_logit[NE + e] - g_nmax[NB + o]);
    g_alpha[e] = es;
    g_alpha[NE + e] = eo;
    atomicAdd(&g_denom[s], es);
    atomicAdd(&g_denom[NB + o], eo);
}

__global__ void salpha_kernel() {
    int i = blockIdx.x * blockDim.x + threadIdx.x;
    if (i >= 2 * NB) return;
    float d = g_denom[i];
    g_salpha[i] = d / (d + 1e-9f);
}

// ---------------- weighted scatter (interleaved wsum layout) ----------------
__global__ __launch_bounds__(256)
void scatter_kernel(const float* __restrict__ rel, const int* __restrict__ sub,
                    const int* __restrict__ obj) {
    const int e = blockIdx.x;
    const int tid = threadIdx.x;
    const int s = sub[e], o = obj[e];
    const float as = g_alpha[e] / (g_denom[s] + 1e-9f);
    const float ao = g_alpha[NE + e] / (g_denom[NB + o] + 1e-9f);

    const float4* r = (const float4*)(rel + (size_t)e * FD);
    float* ws = g_wsum + (size_t)s * (2 * FD);
    float* wo = g_wsum + (size_t)o * (2 * FD) + FD;
    for (int i = tid; i < FD / 4; i += blockDim.x) {
        float4 v = r[i];
        int c = i * 4;
        atomicAdd(&ws[c + 0], as * v.x);
        atomicAdd(&ws[c + 1], as * v.y);
        atomicAdd(&ws[c + 2], as * v.z);
        atomicAdd(&ws[c + 3], as * v.w);
        atomicAdd(&wo[c + 0], ao * v.x);
        atomicAdd(&wo[c + 1], ao * v.y);
        atomicAdd(&wo[c + 2], ao * v.z);
        atomicAdd(&wo[c + 3], ao * v.w);
    }
}

// ---------------- acc init with biases ----------------
__global__ void biasinit_kernel(const float* __restrict__ b_box,
                                const float* __restrict__ b_sub,
                                const float* __restrict__ b_obj) {
    size_t idx = (size_t)blockIdx.x * blockDim.x + threadIdx.x;
    if (idx >= (size_t)NB * OD) return;
    int i = (int)(idx / OD);
    int n = (int)(idx % OD);
    g_acc[idx] = b_box[n] + g_salpha[i] * b_sub[n] + g_salpha[NB + i] * b_obj[n];
}

// ---------------- launch ----------------
static inline void split(const float* src, __half* hi, __half* lo, long n) {
    split_kernel<<<(int)((n / 4 + 255) / 256), 256>>>(src, hi, lo, n);
}
static inline void splith(const float* src, __half* hi, long n) {
    splith_kernel<<<(int)((n / 4 + 255) / 256), 256>>>(src, hi, n);
}

extern "C" void kernel_launch(void* const* d_in, const int* in_sizes, int n_in,
                              void* d_out, int out_size) {
    const float* box_feats = (const float*)d_in[0];
    const float* rel_feats = (const float*)d_in[1];
    const int*   edge_sub  = (const int*)d_in[2];
    const int*   edge_obj  = (const int*)d_in[3];
    const float* W_box  = (const float*)d_in[4];
    const float* b_box  = (const float*)d_in[5];
    const float* W_sub  = (const float*)d_in[6];
    const float* b_sub  = (const float*)d_in[7];
    const float* W_obj  = (const float*)d_in[8];
    const float* b_obj  = (const float*)d_in[9];
    const float* Wa_box = (const float*)d_in[10];
    const float* Wa_rel = (const float*)d_in[11];
    const float* b_a1   = (const float*)d_in[12];
    const float* Wa2    = (const float*)d_in[13];
    const float* b_a2   = (const float*)d_in[14];
    float* out = (float*)d_out;

    float *box_att, *acc, *wsum;
    cudaGetSymbolAddress((void**)&box_att, g_box_att);
    cudaGetSymbolAddress((void**)&acc, g_acc);
    cudaGetSymbolAddress((void**)&wsum, g_wsum);

    __half *relh, *boxh, *boxl, *wsh, *wsl;
    __half *Wabh, *Warh, *Wbh, *Wch;
    cudaGetSymbolAddress((void**)&relh, g_relh);
    cudaGetSymbolAddress((void**)&boxh, g_boxh); cudaGetSymbolAddress((void**)&boxl, g_boxl);
    cudaGetSymbolAddress((void**)&wsh,  g_wsh);  cudaGetSymbolAddress((void**)&wsl,  g_wsl);
    cudaGetSymbolAddress((void**)&Wabh, g_Wabh);
    cudaGetSymbolAddress((void**)&Warh, g_Warh);
    cudaGetSymbolAddress((void**)&Wbh,  g_Wbh);
    cudaGetSymbolAddress((void**)&Wch,  g_Wch);

    init_kernel<<<2048, 256>>>(b_a2);

    // splits: A-side (box, wsum) hi/lo; everything else hi-only
    split(box_feats, boxh, boxl, (long)NB * OD);
    splith(rel_feats, relh, (long)NE * FD);
    splith(Wa_box, Wabh, (long)OD * OD);
    splith(Wa_rel, Warh, (long)FD * OD);
    splith(W_box,  Wbh,  (long)OD * OD);
    splith(W_sub,  Wch,  (long)FD * OD);
    splith(W_obj,  Wch + (size_t)FD * OD, (long)FD * OD);

    // box_att = box_feats @ Wa_box   (fp16 1-product, logit path)
    mma_gemm<1><<<dim3(OD / 128, NB / 128), 256>>>(
        boxh, nullptr, Wabh, nullptr, box_att, NB, OD, OD, 0);

    // fused: logits += partial dot over relu(rel@Wa_rel + box_att[idx] + b_a1) . Wa2
    rel_logit_gemm<<<dim3(OD / 256, NE / 128), 512>>>(
        relh, Warh, edge_sub, edge_obj, b_a1, Wa2, NE, OD, FD);

    segmax_kernel<<<(NE + 255) / 256, 256>>>(edge_sub, edge_obj);
    expsum_kernel<<<(NE + 255) / 256, 256>>>(edge_sub, edge_obj);
    salpha_kernel<<<(2 * NB + 255) / 256, 256>>>();
    scatter_kernel<<<NE, 256>>>(rel_feats, edge_sub, edge_obj);

    split(wsum, wsh, wsl, 2L * NB * FD);

    biasinit_kernel<<<(int)(((size_t)NB * OD + 255) / 256), 256>>>(b_box, b_sub, b_obj);

    // acc += box_feats @ W_box ; out = relu(acc + wsum_cat @ [W_sub; W_obj])  (fp16 2-product)
    mma_gemm<2><<<dim3(OD / 128, NB / 128), 256>>>(
        boxh, boxl, Wbh, acc, acc, NB, OD, OD, 0);
    mma_gemm<2><<<dim3(OD / 128, NB / 128), 256>>>(
        wsh, wsl, Wch, acc, out, NB, OD, 2 * FD, 1);
}

// round 12
// speedup vs baseline: 1.8887x; 1.1378x over previous
#include <cuda_runtime.h>
#include <cuda_fp16.h>
#include <math.h>
#include <stdint.h>

#define NB 4096      // boxes
#define NE 32768     // edges
#define OD 2048      // obj_dim
#define FD 2432      // feats_dim
#define KV (OD + 2 * FD)   // 6912: fused value-GEMM K

// ---------------- static scratch (no cudaMalloc allowed) ----------------
__device__ float g_box_att[(size_t)NB * OD];
__device__ float g_logit[2 * NE];
__device__ float g_alpha[2 * NE];
__device__ float g_nmax[2 * NB];
__device__ float g_denom[2 * NB];
__device__ float g_salpha[2 * NB];
__device__ float g_wsum[2ull * NB * FD];       // per node: [s FD | o FD]

// fp16 buffers (all hi-only now)
__device__ __half g_relh[(size_t)NE * FD];
__device__ __half g_boxh[(size_t)NB * OD];
__device__ __half g_wsh[2ull * NB * FD];
__device__ __half g_Wabh[(size_t)OD * OD];
__device__ __half g_Warh[(size_t)FD * OD];
__device__ __half g_WC[(size_t)KV * OD];       // [W_box; W_sub; W_obj]

// ---------------- init ----------------
__global__ void init_kernel(const float* __restrict__ b_a2) {
    size_t idx = (size_t)blockIdx.x * blockDim.x + threadIdx.x;
    size_t stride = (size_t)gridDim.x * blockDim.x;
    for (size_t i = idx; i < 2ull * NB * FD; i += stride) g_wsum[i] = 0.f;
    float ba2 = b_a2[0];
    for (size_t i = idx; i < 2 * NE; i += stride) g_logit[i] = ba2;
    for (size_t i = idx; i < 2 * NB; i += stride) {
        g_denom[i] = 0.f;
        g_nmax[i] = -INFINITY;
    }
}

// ---------------- fp32 -> fp16 ----------------
__global__ void splith_kernel(const float* __restrict__ src,
                              __half* __restrict__ hi, long n) {
    long i = ((long)blockIdx.x * blockDim.x + threadIdx.x) * 4;
    if (i >= n) return;
    float4 v = *(const float4*)(src + i);
    __half h[4];
    h[0] = __float2half_rn(v.x);
    h[1] = __float2half_rn(v.y);
    h[2] = __float2half_rn(v.z);
    h[3] = __float2half_rn(v.w);
    *(uint2*)(hi + i) = *(uint2*)h;
}

// ---------------- MMA helpers ----------------
__device__ __forceinline__ uint32_t sptr(const void* p) {
    return (uint32_t)__cvta_generic_to_shared(p);
}
__device__ __forceinline__ void ldm4(uint32_t* r, uint32_t a) {
    asm volatile("ldmatrix.sync.aligned.m8n8.x4.shared.b16 {%0,%1,%2,%3}, [%4];"
        : "=r"(r[0]), "=r"(r[1]), "=r"(r[2]), "=r"(r[3]) : "r"(a));
}
__device__ __forceinline__ void ldm4t(uint32_t* r, uint32_t a) {
    asm volatile("ldmatrix.sync.aligned.m8n8.x4.trans.shared.b16 {%0,%1,%2,%3}, [%4];"
        : "=r"(r[0]), "=r"(r[1]), "=r"(r[2]), "=r"(r[3]) : "r"(a));
}
__device__ __forceinline__ void mma16816(float* c, const uint32_t* a, const uint32_t* b) {
    asm volatile("mma.sync.aligned.m16n8k16.row.col.f32.f16.f16.f32 "
        "{%0,%1,%2,%3}, {%4,%5,%6,%7}, {%8,%9}, {%0,%1,%2,%3};"
        : "+f"(c[0]), "+f"(c[1]), "+f"(c[2]), "+f"(c[3])
        : "r"(a[0]), "r"(a[1]), "r"(a[2]), "r"(a[3]), "r"(b[0]), "r"(b[1]));
}

#define LDA 40
#define LDB 136

// ---------------- plain fp16 GEMM (box_att) ----------------
__global__ __launch_bounds__(256, 2)
void mma_gemm(const __half* __restrict__ Ah, const __half* __restrict__ Bh,
              float* __restrict__ Cout, int M, int N, int K) {
    __shared__ __half sAh[128 * LDA];
    __shared__ __half sBh[32 * LDB];

    const int tid  = threadIdx.x;
    const int lane = tid & 31;
    const int wid  = tid >> 5;
    const int wm   = wid & 1;
    const int wn   = wid >> 1;
    const int bm   = blockIdx.y * 128;
    const int bn   = blockIdx.x * 128;

    float acc[4][4][4];
    #pragma unroll
    for (int i = 0; i < 4; i++)
        #pragma unroll
        for (int j = 0; j < 4; j++)
            #pragma unroll
            for (int q = 0; q < 4; q++) acc[i][j][q] = 0.f;

    for (int k0 = 0; k0 < K; k0 += 32) {
        #pragma unroll
        for (int p = 0; p < 2; p++) {
            int u  = tid + p * 256;
            int r  = u >> 2,  cg = (u & 3) << 3;
            int rb = u >> 4,  cb = (u & 15) << 3;
            *(uint4*)&sAh[r * LDA + cg]  = *(const uint4*)(Ah + (size_t)(bm + r) * K + k0 + cg);
            *(uint4*)&sBh[rb * LDB + cb] = *(const uint4*)(Bh + (size_t)(k0 + rb) * N + bn + cb);
        }
        __syncthreads();

        #pragma unroll
        for (int ks = 0; ks < 32; ks += 16) {
            uint32_t bh[2][4];
            #pragma unroll
            for (int nh = 0; nh < 2; nh++) {
                int rr = ks + (lane & 15);
                int cc = wn * 32 + nh * 16 + ((lane >> 4) << 3);
                ldm4t(bh[nh], sptr(&sBh[rr * LDB + cc]));
            }
            #pragma unroll
            for (int mt = 0; mt < 4; mt++) {
                uint32_t ah[4];
                int ar = wm * 64 + mt * 16 + (lane & 15);
                int ac = ks + ((lane >> 4) << 3);
                ldm4(ah, sptr(&sAh[ar * LDA + ac]));
                #pragma unroll
                for (int nt = 0; nt < 4; nt++)
                    mma16816(acc[mt][nt], ah, &bh[nt >> 1][(nt & 1) * 2]);
            }
        }
        __syncthreads();
    }

    const int r0 = bm + wm * 64;
    const int c0 = bn + wn * 32;
    #pragma unroll
    for (int mt = 0; mt < 4; mt++) {
        #pragma unroll
        for (int nt = 0; nt < 4; nt++) {
            int row = r0 + mt * 16 + (lane >> 2);
            int col = c0 + nt * 8 + ((lane & 3) << 1);
            *(float2*)(Cout + (size_t)row * N + col) =
                make_float2(acc[mt][nt][0], acc[mt][nt][1]);
            *(float2*)(Cout + (size_t)(row + 8) * N + col) =
                make_float2(acc[mt][nt][2], acc[mt][nt][3]);
        }
    }
}

// ---------------- fused value GEMM: out = relu(bias + [box|wsum] @ WC) ----------
// A segmented: k<OD from Abox (stride OD), else from Aws (stride 2FD).
__global__ __launch_bounds__(256, 2)
void value_gemm(const __half* __restrict__ Abox, const __half* __restrict__ Aws,
                const __half* __restrict__ B,
                const float* __restrict__ b_box, const float* __restrict__ b_sub,
                const float* __restrict__ b_obj, float* __restrict__ out) {
    __shared__ __half sAh[128 * LDA];
    __shared__ __half sBh[32 * LDB];

    const int tid  = threadIdx.x;
    const int lane = tid & 31;
    const int wid  = tid >> 5;
    const int wm   = wid & 1;
    const int wn   = wid >> 1;
    const int bm   = blockIdx.y * 128;
    const int bn   = blockIdx.x * 128;

    float acc[4][4][4];
    #pragma unroll
    for (int i = 0; i < 4; i++)
        #pragma unroll
        for (int j = 0; j < 4; j++)
            #pragma unroll
            for (int q = 0; q < 4; q++) acc[i][j][q] = 0.f;

    for (int k0 = 0; k0 < KV; k0 += 32) {
        const bool seg0 = (k0 < OD);
        #pragma unroll
        for (int p = 0; p < 2; p++) {
            int u  = tid + p * 256;
            int r  = u >> 2,  cg = (u & 3) << 3;
            int rb = u >> 4,  cb = (u & 15) << 3;
            const __half* asrc = seg0
                ? Abox + (size_t)(bm + r) * OD + k0 + cg
                : Aws + (size_t)(bm + r) * (2 * FD) + (k0 - OD) + cg;
            *(uint4*)&sAh[r * LDA + cg]  = *(const uint4*)asrc;
            *(uint4*)&sBh[rb * LDB + cb] = *(const uint4*)(B + (size_t)(k0 + rb) * OD + bn + cb);
        }
        __syncthreads();

        #pragma unroll
        for (int ks = 0; ks < 32; ks += 16) {
            uint32_t bh[2][4];
            #pragma unroll
            for (int nh = 0; nh < 2; nh++) {
                int rr = ks + (lane & 15);
                int cc = wn * 32 + nh * 16 + ((lane >> 4) << 3);
                ldm4t(bh[nh], sptr(&sBh[rr * LDB + cc]));
            }
            #pragma unroll
            for (int mt = 0; mt < 4; mt++) {
                uint32_t ah[4];
                int ar = wm * 64 + mt * 16 + (lane & 15);
                int ac = ks + ((lane >> 4) << 3);
                ldm4(ah, sptr(&sAh[ar * LDA + ac]));
                #pragma unroll
                for (int nt = 0; nt < 4; nt++)
                    mma16816(acc[mt][nt], ah, &bh[nt >> 1][(nt & 1) * 2]);
            }
        }
        __syncthreads();
    }

    const int r0 = bm + wm * 64;
    const int c0 = bn + wn * 32;
    #pragma unroll
    for (int mt = 0; mt < 4; mt++) {
        int rowA = r0 + mt * 16 + (lane >> 2);
        int rowB = rowA + 8;
        float saA = g_salpha[rowA], soA = g_salpha[NB + rowA];
        float saB = g_salpha[rowB], soB = g_salpha[NB + rowB];
        #pragma unroll
        for (int nt = 0; nt < 4; nt++) {
            int col = c0 + nt * 8 + ((lane & 3) << 1);
            float2 bb = *(const float2*)(b_box + col);
            float2 bs = *(const float2*)(b_sub + col);
            float2 bo = *(const float2*)(b_obj + col);
            float2 vA = make_float2(
                fmaxf(acc[mt][nt][0] + bb.x + saA * bs.x + soA * bo.x, 0.f),
                fmaxf(acc[mt][nt][1] + bb.y + saA * bs.y + soA * bo.y, 0.f));
            float2 vB = make_float2(
                fmaxf(acc[mt][nt][2] + bb.x + saB * bs.x + soB * bo.x, 0.f),
                fmaxf(acc[mt][nt][3] + bb.y + saB * bs.y + soB * bo.y, 0.f));
            *(float2*)(out + (size_t)rowA * OD + col) = vA;
            *(float2*)(out + (size_t)rowB * OD + col) = vB;
        }
    }
}

// ---------------- rel GEMM with fused logit epilogue ----------------
#define RLDB 264

__global__ __launch_bounds__(512, 1)
void rel_logit_gemm(const __half* __restrict__ Ah,
                    const __half* __restrict__ Bh,
                    const int* __restrict__ sub, const int* __restrict__ obj,
                    const float* __restrict__ b_a1, const float* __restrict__ Wa2,
                    int M, int N, int K) {
    __shared__ __half sA[128 * LDA];
    __shared__ __half sB[32 * RLDB];

    const int tid  = threadIdx.x;
    const int lane = tid & 31;
    const int wid  = tid >> 5;
    const int wm   = wid & 3;
    const int wn   = wid >> 2;
    const int bm   = blockIdx.y * 128;
    const int bn   = blockIdx.x * 256;

    float acc[2][8][4];
    #pragma unroll
    for (int i = 0; i < 2; i++)
        #pragma unroll
        for (int j = 0; j < 8; j++)
            #pragma unroll
            for (int q = 0; q < 4; q++) acc[i][j][q] = 0.f;

    for (int k0 = 0; k0 < K; k0 += 32) {
        {
            int r = tid >> 2, cg = (tid & 3) << 3;
            *(uint4*)&sA[r * LDA + cg] = *(const uint4*)(Ah + (size_t)(bm + r) * K + k0 + cg);
            #pragma unroll
            for (int p = 0; p < 2; p++) {
                int u = tid + (p << 9);
                int rb = u >> 5, cb = (u & 31) << 3;
                *(uint4*)&sB[rb * RLDB + cb] = *(const uint4*)(Bh + (size_t)(k0 + rb) * N + bn + cb);
            }
        }
        __syncthreads();

        #pragma unroll
        for (int ks = 0; ks < 32; ks += 16) {
            uint32_t bfr[4][4];
            #pragma unroll
            for (int nh = 0; nh < 4; nh++) {
                int rr = ks + (lane & 15);
                int cc = wn * 64 + nh * 16 + ((lane >> 4) << 3);
                ldm4t(bfr[nh], sptr(&sB[rr * RLDB + cc]));
            }
            #pragma unroll
            for (int mt = 0; mt < 2; mt++) {
                uint32_t a[4];
                int ar = wm * 32 + mt * 16 + (lane & 15);
                int ac = ks + ((lane >> 4) << 3);
                ldm4(a, sptr(&sA[ar * LDA + ac]));
                #pragma unroll
                for (int nt = 0; nt < 8; nt++)
                    mma16816(acc[mt][nt], a, &bfr[nt >> 1][(nt & 1) * 2]);
            }
        }
        __syncthreads();
    }

    // fused logit epilogue
    float ps[4] = {0.f, 0.f, 0.f, 0.f}, po[4] = {0.f, 0.f, 0.f, 0.f};
    int rows[4], si[4], oi[4];
    #pragma unroll
    for (int i = 0; i < 4; i++) {
        int mt = i >> 1, h = i & 1;
        rows[i] = bm + wm * 32 + mt * 16 + (lane >> 2) + h * 8;
        si[i] = sub[rows[i]];
        oi[i] = obj[rows[i]];
    }
    #pragma unroll
    for (int nt = 0; nt < 8; nt++) {
        int c = bn + wn * 64 + nt * 8 + ((lane & 3) << 1);
        float2 wv = *(const float2*)(Wa2 + c);
        float2 bv = *(const float2*)(b_a1 + c);
        #pragma unroll
        for (int i = 0; i < 4; i++) {
            int mt = i >> 1, h = i & 1;
            float a0 = acc[mt][nt][h * 2 + 0];
            float a1 = acc[mt][nt][h * 2 + 1];
            float2 bsv = *(const float2*)(g_box_att + (size_t)si[i] * OD + c);
            float2 bov = *(const float2*)(g_box_att + (size_t)oi[i] * OD + c);
            ps[i] = fmaf(fmaxf(a0 + bsv.x + bv.x, 0.f), wv.x, ps[i]);
            ps[i] = fmaf(fmaxf(a1 + bsv.y + bv.y, 0.f), wv.y, ps[i]);
            po[i] = fmaf(fmaxf(a0 + bov.x + bv.x, 0.f), wv.x, po[i]);
            po[i] = fmaf(fmaxf(a1 + bov.y + bv.y, 0.f), wv.y, po[i]);
        }
    }
    #pragma unroll
    for (int i = 0; i < 4; i++) {
        ps[i] += __shfl_xor_sync(0xffffffffu, ps[i], 1);
        ps[i] += __shfl_xor_sync(0xffffffffu, ps[i], 2);
        po[i] += __shfl_xor_sync(0xffffffffu, po[i], 1);
        po[i] += __shfl_xor_sync(0xffffffffu, po[i], 2);
        if ((lane & 3) == 0) {
            atomicAdd(&g_logit[rows[i]], ps[i]);
            atomicAdd(&g_logit[NE + rows[i]], po[i]);
        }
    }
}

// ---------------- segment softmax ----------------
__device__ __forceinline__ void atomicMaxF(float* addr, float v) {
    if (v >= 0.f) atomicMax((int*)addr, __float_as_int(v));
    else          atomicMin((unsigned int*)addr, __float_as_uint(v));
}

__global__ void segmax_kernel(const int* __restrict__ sub, const int* __restrict__ obj) {
    int e = blockIdx.x * blockDim.x + threadIdx.x;
    if (e >= NE) return;
    atomicMaxF(&g_nmax[sub[e]], g_logit[e]);
    atomicMaxF(&g_nmax[NB + obj[e]], g_logit[NE + e]);
}

__global__ void expsum_kernel(const int* __restrict__ sub, const int* __restrict__ obj) {
    int e = blockIdx.x * blockDim.x + threadIdx.x;
    if (e >= NE) return;
    int s = sub[e], o = obj[e];
    float es = expf(g_logit[e] - g_nmax[s]);
    float eo = expf(g_logit[NE + e] - g_nmax[NB + o]);
    g_alpha[e] = es;
    g_alpha[NE + e] = eo;
    atomicAdd(&g_denom[s], es);
    atomicAdd(&g_denom[NB + o], eo);
}

__global__ void salpha_kernel() {
    int i = blockIdx.x * blockDim.x + threadIdx.x;
    if (i >= 2 * NB) return;
    float d = g_denom[i];
    g_salpha[i] = d / (d + 1e-9f);
}

// ---------------- weighted scatter (interleaved wsum layout) ----------------
__global__ __launch_bounds__(256)
void scatter_kernel(const float* __restrict__ rel, const int* __restrict__ sub,
                    const int* __restrict__ obj) {
    const int e = blockIdx.x;
    const int tid = threadIdx.x;
    const int s = sub[e], o = obj[e];
    const float as = g_alpha[e] / (g_denom[s] + 1e-9f);
    const float ao = g_alpha[NE + e] / (g_denom[NB + o] + 1e-9f);

    const float4* r = (const float4*)(rel + (size_t)e * FD);
    float* ws = g_wsum + (size_t)s * (2 * FD);
    float* wo = g_wsum + (size_t)o * (2 * FD) + FD;
    for (int i = tid; i < FD / 4; i += blockDim.x) {
        float4 v = r[i];
        int c = i * 4;
        atomicAdd(&ws[c + 0], as * v.x);
        atomicAdd(&ws[c + 1], as * v.y);
        atomicAdd(&ws[c + 2], as * v.z);
        atomicAdd(&ws[c + 3], as * v.w);
        atomicAdd(&wo[c + 0], ao * v.x);
        atomicAdd(&wo[c + 1], ao * v.y);
        atomicAdd(&wo[c + 2], ao * v.z);
        atomicAdd(&wo[c + 3], ao * v.w);
    }
}

// ---------------- launch ----------------
static inline void splith(const float* src, __half* hi, long n) {
    splith_kernel<<<(int)((n / 4 + 255) / 256), 256>>>(src, hi, n);
}

extern "C" void kernel_launch(void* const* d_in, const int* in_sizes, int n_in,
                              void* d_out, int out_size) {
    const float* box_feats = (const float*)d_in[0];
    const float* rel_feats = (const float*)d_in[1];
    const int*   edge_sub  = (const int*)d_in[2];
    const int*   edge_obj  = (const int*)d_in[3];
    const float* W_box  = (const float*)d_in[4];
    const float* b_box  = (const float*)d_in[5];
    const float* W_sub  = (const float*)d_in[6];
    const float* b_sub  = (const float*)d_in[7];
    const float* W_obj  = (const float*)d_in[8];
    const float* b_obj  = (const float*)d_in[9];
    const float* Wa_box = (const float*)d_in[10];
    const float* Wa_rel = (const float*)d_in[11];
    const float* b_a1   = (const float*)d_in[12];
    const float* Wa2    = (const float*)d_in[13];
    const float* b_a2   = (const float*)d_in[14];
    float* out = (float*)d_out;

    float *box_att, *wsum;
    cudaGetSymbolAddress((void**)&box_att, g_box_att);
    cudaGetSymbolAddress((void**)&wsum, g_wsum);

    __half *relh, *boxh, *wsh, *Wabh, *Warh, *WC;
    cudaGetSymbolAddress((void**)&relh, g_relh);
    cudaGetSymbolAddress((void**)&boxh, g_boxh);
    cudaGetSymbolAddress((void**)&wsh,  g_wsh);
    cudaGetSymbolAddress((void**)&Wabh, g_Wabh);
    cudaGetSymbolAddress((void**)&Warh, g_Warh);
    cudaGetSymbolAddress((void**)&WC,   g_WC);

    init_kernel<<<2048, 256>>>(b_a2);

    // splits (all hi-only fp16)
    splith(box_feats, boxh, (long)NB * OD);
    splith(rel_feats, relh, (long)NE * FD);
    splith(Wa_box, Wabh, (long)OD * OD);
    splith(Wa_rel, Warh, (long)FD * OD);
    splith(W_box,  WC,                                (long)OD * OD);
    splith(W_sub,  WC + (size_t)OD * OD,              (long)FD * OD);
    splith(W_obj,  WC + (size_t)(OD + FD) * OD,       (long)FD * OD);

    // box_att = box_feats @ Wa_box   (fp16, logit path)
    mma_gemm<<<dim3(OD / 128, NB / 128), 256>>>(boxh, Wabh, box_att, NB, OD, OD);

    // fused: logits += partial dot over relu(rel@Wa_rel + box_att[idx] + b_a1) . Wa2
    rel_logit_gemm<<<dim3(OD / 256, NE / 128), 512>>>(
        relh, Warh, edge_sub, edge_obj, b_a1, Wa2, NE, OD, FD);

    segmax_kernel<<<(NE + 255) / 256, 256>>>(edge_sub, edge_obj);
    expsum_kernel<<<(NE + 255) / 256, 256>>>(edge_sub, edge_obj);
    salpha_kernel<<<(2 * NB + 255) / 256, 256>>>();
    scatter_kernel<<<NE, 256>>>(rel_feats, edge_sub, edge_obj);

    splith(wsum, wsh, 2L * NB * FD);

    // fused value GEMM: out = relu(bias + [box | wsum_s | wsum_o] @ [W_box; W_sub; W_obj])
    value_gemm<<<dim3(OD / 128, NB / 128), 256>>>(
        boxh, wsh, WC, b_box, b_sub, b_obj, out);
}

// round 15
// speedup vs baseline: 2.1910x; 1.1600x over previous
#include <cuda_runtime.h>
#include <cuda_fp16.h>
#include <math.h>
#include <stdint.h>

#define NB 4096      // boxes
#define NE 32768     // edges
#define OD 2048      // obj_dim
#define FD 2432      // feats_dim
#define KV (OD + 2 * FD)   // 6912: fused value-GEMM K

// ---------------- static scratch (no cudaMalloc allowed) ----------------
__device__ float g_box_att[(size_t)NB * OD];
__device__ float g_logit[2 * NE];
__device__ float g_alpha[2 * NE];
__device__ float g_nmax[2 * NB];
__device__ float g_denom[2 * NB];
__device__ float g_salpha[2 * NB];

// CSR edge lists (both directions in one 2*NB-segment table: [0,NB)=sub, [NB,2NB)=obj)
__device__ int g_cnt[2 * NB];          // counts, then reused as fill cursors
__device__ int g_off[2 * NB + 1];
__device__ int g_eid[2 * NE];

// fp16 buffers
__device__ __half g_relh[(size_t)NE * FD];
__device__ __half g_boxh[(size_t)NB * OD];
__device__ __half g_wsh[2ull * NB * FD];       // per node: [s FD | o FD], written by gather
__device__ __half g_Wabh[(size_t)OD * OD];
__device__ __half g_Warh[(size_t)FD * OD];
__device__ __half g_WC[(size_t)KV * OD];       // [W_box; W_sub; W_obj]

// ---------------- init ----------------
__global__ void init_kernel(const float* __restrict__ b_a2) {
    size_t idx = (size_t)blockIdx.x * blockDim.x + threadIdx.x;
    size_t stride = (size_t)gridDim.x * blockDim.x;
    float ba2 = b_a2[0];
    for (size_t i = idx; i < 2 * NE; i += stride) g_logit[i] = ba2;
    for (size_t i = idx; i < 2 * NB; i += stride) {
        g_denom[i] = 0.f;
        g_nmax[i] = -INFINITY;
        g_cnt[i] = 0;
    }
}

// ---------------- fp32 -> fp16 ----------------
__global__ void splith_kernel(const float* __restrict__ src,
                              __half* __restrict__ hi, long n) {
    long i = ((long)blockIdx.x * blockDim.x + threadIdx.x) * 4;
    if (i >= n) return;
    float4 v = *(const float4*)(src + i);
    __half h[4];
    h[0] = __float2half_rn(v.x);
    h[1] = __float2half_rn(v.y);
    h[2] = __float2half_rn(v.z);
    h[3] = __float2half_rn(v.w);
    *(uint2*)(hi + i) = *(uint2*)h;
}

// ---------------- CSR build ----------------
__global__ void count_kernel(const int* __restrict__ sub, const int* __restrict__ obj) {
    int e = blockIdx.x * blockDim.x + threadIdx.x;
    if (e >= NE) return;
    atomicAdd(&g_cnt[sub[e]], 1);
    atomicAdd(&g_cnt[NB + obj[e]], 1);
}

// single-block exclusive scan over 2*NB = 8192 counts
__global__ __launch_bounds__(1024)
void scan_kernel() {
    __shared__ int sh[2 * NB];
    __shared__ int ps[1024];
    const int tid = threadIdx.x;
    for (int i = tid; i < 2 * NB; i += 1024) sh[i] = g_cnt[i];
    __syncthreads();
    const int base = tid * 8;
    int loc[8], s = 0;
    #pragma unroll
    for (int j = 0; j < 8; j++) { loc[j] = s; s += sh[base + j]; }
    ps[tid] = s;
    __syncthreads();
    #pragma unroll
    for (int off = 1; off < 1024; off <<= 1) {
        int v = (tid >= off) ? ps[tid - off] : 0;
        __syncthreads();
        ps[tid] += v;
        __syncthreads();
    }
    int excl = ps[tid] - s;
    #pragma unroll
    for (int j = 0; j < 8; j++) {
        g_off[base + j] = excl + loc[j];
        g_cnt[base + j] = excl + loc[j];   // reuse as fill cursor
    }
    if (tid == 0) g_off[2 * NB] = 2 * NE;
}

__global__ void fill_kernel(const int* __restrict__ sub, const int* __restrict__ obj) {
    int e = blockIdx.x * blockDim.x + threadIdx.x;
    if (e >= NE) return;
    int ps = atomicAdd(&g_cnt[sub[e]], 1);
    g_eid[ps] = e;
    int po = atomicAdd(&g_cnt[NB + obj[e]], 1);
    g_eid[po] = e;
}

// ---------------- CSR gather: wsh[node,part] = fp16( sum_e alpha_e * relh[e] ) ----
__global__ __launch_bounds__(256)
void gather_kernel() {
    const int node = blockIdx.x;           // [0,2NB): <NB = sub part, >=NB = obj part
    const int tid = threadIdx.x;
    const int beg = g_off[node], end = g_off[node + 1];
    const float inv = 1.f / (g_denom[node] + 1e-9f);
    const bool isSub = node < NB;

    float acc[3][4];
    #pragma unroll
    for (int j = 0; j < 3; j++)
        #pragma unroll
        for (int q = 0; q < 4; q++) acc[j][q] = 0.f;

    for (int t = beg; t < end; t++) {
        int e = g_eid[t];
        float a = g_alpha[isSub ? e : NE + e] * inv;
        const __half* r = g_relh + (size_t)e * FD;
        #pragma unroll
        for (int j = 0; j < 3; j++) {
            int f = tid * 4 + j * 1024;
            if (f < FD) {
                uint2 u = *(const uint2*)(r + f);
                float2 p0 = __half22float2(*(__half2*)&u.x);
                float2 p1 = __half22float2(*(__half2*)&u.y);
                acc[j][0] = fmaf(a, p0.x, acc[j][0]);
                acc[j][1] = fmaf(a, p0.y, acc[j][1]);
                acc[j][2] = fmaf(a, p1.x, acc[j][2]);
                acc[j][3] = fmaf(a, p1.y, acc[j][3]);
            }
        }
    }

    const int n = isSub ? node : node - NB;
    __half* w = g_wsh + (size_t)n * (2 * FD) + (isSub ? 0 : FD);
    #pragma unroll
    for (int j = 0; j < 3; j++) {
        int f = tid * 4 + j * 1024;
        if (f < FD) {
            __half h[4];
            h[0] = __float2half_rn(acc[j][0]);
            h[1] = __float2half_rn(acc[j][1]);
            h[2] = __float2half_rn(acc[j][2]);
            h[3] = __float2half_rn(acc[j][3]);
            *(uint2*)(w + f) = *(uint2*)h;
        }
    }
}

// ---------------- MMA helpers ----------------
__device__ __forceinline__ uint32_t sptr(const void* p) {
    return (uint32_t)__cvta_generic_to_shared(p);
}
__device__ __forceinline__ void ldm4(uint32_t* r, uint32_t a) {
    asm volatile("ldmatrix.sync.aligned.m8n8.x4.shared.b16 {%0,%1,%2,%3}, [%4];"
        : "=r"(r[0]), "=r"(r[1]), "=r"(r[2]), "=r"(r[3]) : "r"(a));
}
__device__ __forceinline__ void ldm4t(uint32_t* r, uint32_t a) {
    asm volatile("ldmatrix.sync.aligned.m8n8.x4.trans.shared.b16 {%0,%1,%2,%3}, [%4];"
        : "=r"(r[0]), "=r"(r[1]), "=r"(r[2]), "=r"(r[3]) : "r"(a));
}
__device__ __forceinline__ void mma16816(float* c, const uint32_t* a, const uint32_t* b) {
    asm volatile("mma.sync.aligned.m16n8k16.row.col.f32.f16.f16.f32 "
        "{%0,%1,%2,%3}, {%4,%5,%6,%7}, {%8,%9}, {%0,%1,%2,%3};"
        : "+f"(c[0]), "+f"(c[1]), "+f"(c[2]), "+f"(c[3])
        : "r"(a[0]), "r"(a[1]), "r"(a[2]), "r"(a[3]), "r"(b[0]), "r"(b[1]));
}

#define LDA 40
#define LDB 136

// ---------------- plain fp16 GEMM (box_att) ----------------
__global__ __launch_bounds__(256, 2)
void mma_gemm(const __half* __restrict__ Ah, const __half* __restrict__ Bh,
              float* __restrict__ Cout, int M, int N, int K) {
    __shared__ __half sAh[128 * LDA];
    __shared__ __half sBh[32 * LDB];

    const int tid  = threadIdx.x;
    const int lane = tid & 31;
    const int wid  = tid >> 5;
    const int wm   = wid & 1;
    const int wn   = wid >> 1;
    const int bm   = blockIdx.y * 128;
    const int bn   = blockIdx.x * 128;

    float acc[4][4][4];
    #pragma unroll
    for (int i = 0; i < 4; i++)
        #pragma unroll
        for (int j = 0; j < 4; j++)
            #pragma unroll
            for (int q = 0; q < 4; q++) acc[i][j][q] = 0.f;

    for (int k0 = 0; k0 < K; k0 += 32) {
        #pragma unroll
        for (int p = 0; p < 2; p++) {
            int u  = tid + p * 256;
            int r  = u >> 2,  cg = (u & 3) << 3;
            int rb = u >> 4,  cb = (u & 15) << 3;
            *(uint4*)&sAh[r * LDA + cg]  = *(const uint4*)(Ah + (size_t)(bm + r) * K + k0 + cg);
            *(uint4*)&sBh[rb * LDB + cb] = *(const uint4*)(Bh + (size_t)(k0 + rb) * N + bn + cb);
        }
        __syncthreads();

        #pragma unroll
        for (int ks = 0; ks < 32; ks += 16) {
            uint32_t bh[2][4];
            #pragma unroll
            for (int nh = 0; nh < 2; nh++) {
                int rr = ks + (lane & 15);
                int cc = wn * 32 + nh * 16 + ((lane >> 4) << 3);
                ldm4t(bh[nh], sptr(&sBh[rr * LDB + cc]));
            }
            #pragma unroll
            for (int mt = 0; mt < 4; mt++) {
                uint32_t ah[4];
                int ar = wm * 64 + mt * 16 + (lane & 15);
                int ac = ks + ((lane >> 4) << 3);
                ldm4(ah, sptr(&sAh[ar * LDA + ac]));
                #pragma unroll
                for (int nt = 0; nt < 4; nt++)
                    mma16816(acc[mt][nt], ah, &bh[nt >> 1][(nt & 1) * 2]);
            }
        }
        __syncthreads();
    }

    const int r0 = bm + wm * 64;
    const int c0 = bn + wn * 32;
    #pragma unroll
    for (int mt = 0; mt < 4; mt++) {
        #pragma unroll
        for (int nt = 0; nt < 4; nt++) {
            int row = r0 + mt * 16 + (lane >> 2);
            int col = c0 + nt * 8 + ((lane & 3) << 1);
            *(float2*)(Cout + (size_t)row * N + col) =
                make_float2(acc[mt][nt][0], acc[mt][nt][1]);
            *(float2*)(Cout + (size_t)(row + 8) * N + col) =
                make_float2(acc[mt][nt][2], acc[mt][nt][3]);
        }
    }
}

// ---------------- fused value GEMM: out = relu(bias + [box|wsum] @ WC) ----------
__global__ __launch_bounds__(256, 2)
void value_gemm(const __half* __restrict__ Abox, const __half* __restrict__ Aws,
                const __half* __restrict__ B,
                const float* __restrict__ b_box, const float* __restrict__ b_sub,
                const float* __restrict__ b_obj, float* __restrict__ out) {
    __shared__ __half sAh[128 * LDA];
    __shared__ __half sBh[32 * LDB];

    const int tid  = threadIdx.x;
    const int lane = tid & 31;
    const int wid  = tid >> 5;
    const int wm   = wid & 1;
    const int wn   = wid >> 1;
    const int bm   = blockIdx.y * 128;
    const int bn   = blockIdx.x * 128;

    float acc[4][4][4];
    #pragma unroll
    for (int i = 0; i < 4; i++)
        #pragma unroll
        for (int j = 0; j < 4; j++)
            #pragma unroll
            for (int q = 0; q < 4; q++) acc[i][j][q] = 0.f;

    for (int k0 = 0; k0 < KV; k0 += 32) {
        const bool seg0 = (k0 < OD);
        #pragma unroll
        for (int p = 0; p < 2; p++) {
            int u  = tid + p * 256;
            int r  = u >> 2,  cg = (u & 3) << 3;
            int rb = u >> 4,  cb = (u & 15) << 3;
            const __half* asrc = seg0
                ? Abox + (size_t)(bm + r) * OD + k0 + cg
                : Aws + (size_t)(bm + r) * (2 * FD) + (k0 - OD) + cg;
            *(uint4*)&sAh[r * LDA + cg]  = *(const uint4*)asrc;
            *(uint4*)&sBh[rb * LDB + cb] = *(const uint4*)(B + (size_t)(k0 + rb) * OD + bn + cb);
        }
        __syncthreads();

        #pragma unroll
        for (int ks = 0; ks < 32; ks += 16) {
            uint32_t bh[2][4];
            #pragma unroll
            for (int nh = 0; nh < 2; nh++) {
                int rr = ks + (lane & 15);
                int cc = wn * 32 + nh * 16 + ((lane >> 4) << 3);
                ldm4t(bh[nh], sptr(&sBh[rr * LDB + cc]));
            }
            #pragma unroll
            for (int mt = 0; mt < 4; mt++) {
                uint32_t ah[4];
                int ar = wm * 64 + mt * 16 + (lane & 15);
                int ac = ks + ((lane >> 4) << 3);
                ldm4(ah, sptr(&sAh[ar * LDA + ac]));
                #pragma unroll
                for (int nt = 0; nt < 4; nt++)
                    mma16816(acc[mt][nt], ah, &bh[nt >> 1][(nt & 1) * 2]);
            }
        }
        __syncthreads();
    }

    const int r0 = bm + wm * 64;
    const int c0 = bn + wn * 32;
    #pragma unroll
    for (int mt = 0; mt < 4; mt++) {
        int rowA = r0 + mt * 16 + (lane >> 2);
        int rowB = rowA + 8;
        float saA = g_salpha[rowA], soA = g_salpha[NB + rowA];
        float saB = g_salpha[rowB], soB = g_salpha[NB + rowB];
        #pragma unroll
        for (int nt = 0; nt < 4; nt++) {
            int col = c0 + nt * 8 + ((lane & 3) << 1);
            float2 bb = *(const float2*)(b_box + col);
            float2 bs = *(const float2*)(b_sub + col);
            float2 bo = *(const float2*)(b_obj + col);
            float2 vA = make_float2(
                fmaxf(acc[mt][nt][0] + bb.x + saA * bs.x + soA * bo.x, 0.f),
                fmaxf(acc[mt][nt][1] + bb.y + saA * bs.y + soA * bo.y, 0.f));
            float2 vB = make_float2(
                fmaxf(acc[mt][nt][2] + bb.x + saB * bs.x + soB * bo.x, 0.f),
                fmaxf(acc[mt][nt][3] + bb.y + saB * bs.y + soB * bo.y, 0.f));
            *(float2*)(out + (size_t)rowA * OD + col) = vA;
            *(float2*)(out + (size_t)rowB * OD + col) = vB;
        }
    }
}

// ---------------- rel GEMM with fused logit epilogue ----------------
#define RLDB 264

__global__ __launch_bounds__(512, 1)
void rel_logit_gemm(const __half* __restrict__ Ah,
                    const __half* __restrict__ Bh,
                    const int* __restrict__ sub, const int* __restrict__ obj,
                    const float* __restrict__ b_a1, const float* __restrict__ Wa2,
                    int M, int N, int K) {
    __shared__ __half sA[128 * LDA];
    __shared__ __half sB[32 * RLDB];

    const int tid  = threadIdx.x;
    const int lane = tid & 31;
    const int wid  = tid >> 5;
    const int wm   = wid & 3;
    const int wn   = wid >> 2;
    const int bm   = blockIdx.y * 128;
    const int bn   = blockIdx.x * 256;

    float acc[2][8][4];
    #pragma unroll
    for (int i = 0; i < 2; i++)
        #pragma unroll
        for (int j = 0; j < 8; j++)
            #pragma unroll
            for (int q = 0; q < 4; q++) acc[i][j][q] = 0.f;

    for (int k0 = 0; k0 < K; k0 += 32) {
        {
            int r = tid >> 2, cg = (tid & 3) << 3;
            *(uint4*)&sA[r * LDA + cg] = *(const uint4*)(Ah + (size_t)(bm + r) * K + k0 + cg);
            #pragma unroll
            for (int p = 0; p < 2; p++) {
                int u = tid + (p << 9);
                int rb = u >> 5, cb = (u & 31) << 3;
                *(uint4*)&sB[rb * RLDB + cb] = *(const uint4*)(Bh + (size_t)(k0 + rb) * N + bn + cb);
            }
        }
        __syncthreads();

        #pragma unroll
        for (int ks = 0; ks < 32; ks += 16) {
            uint32_t bfr[4][4];
            #pragma unroll
            for (int nh = 0; nh < 4; nh++) {
                int rr = ks + (lane & 15);
                int cc = wn * 64 + nh * 16 + ((lane >> 4) << 3);
                ldm4t(bfr[nh], sptr(&sB[rr * RLDB + cc]));
            }
            #pragma unroll
            for (int mt = 0; mt < 2; mt++) {
                uint32_t a[4];
                int ar = wm * 32 + mt * 16 + (lane & 15);
                int ac = ks + ((lane >> 4) << 3);
                ldm4(a, sptr(&sA[ar * LDA + ac]));
                #pragma unroll
                for (int nt = 0; nt < 8; nt++)
                    mma16816(acc[mt][nt], a, &bfr[nt >> 1][(nt & 1) * 2]);
            }
        }
        __syncthreads();
    }

    // fused logit epilogue
    float ps[4] = {0.f, 0.f, 0.f, 0.f}, po[4] = {0.f, 0.f, 0.f, 0.f};
    int rows[4], si[4], oi[4];
    #pragma unroll
    for (int i = 0; i < 4; i++) {
        int mt = i >> 1, h = i & 1;
        rows[i] = bm + wm * 32 + mt * 16 + (lane >> 2) + h * 8;
        si[i] = sub[rows[i]];
        oi[i] = obj[rows[i]];
    }
    #pragma unroll
    for (int nt = 0; nt < 8; nt++) {
        int c = bn + wn * 64 + nt * 8 + ((lane & 3) << 1);
        float2 wv = *(const float2*)(Wa2 + c);
        float2 bv = *(const float2*)(b_a1 + c);
        #pragma unroll
        for (int i = 0; i < 4; i++) {
            int mt = i >> 1, h = i & 1;
            float a0 = acc[mt][nt][h * 2 + 0];
            float a1 = acc[mt][nt][h * 2 + 1];
            float2 bsv = *(const float2*)(g_box_att + (size_t)si[i] * OD + c);
            float2 bov = *(const float2*)(g_box_att + (size_t)oi[i] * OD + c);
            ps[i] = fmaf(fmaxf(a0 + bsv.x + bv.x, 0.f), wv.x, ps[i]);
            ps[i] = fmaf(fmaxf(a1 + bsv.y + bv.y, 0.f), wv.y, ps[i]);
            po[i] = fmaf(fmaxf(a0 + bov.x + bv.x, 0.f), wv.x, po[i]);
            po[i] = fmaf(fmaxf(a1 + bov.y + bv.y, 0.f), wv.y, po[i]);
        }
    }
    #pragma unroll
    for (int i = 0; i < 4; i++) {
        ps[i] += __shfl_xor_sync(0xffffffffu, ps[i], 1);
        ps[i] += __shfl_xor_sync(0xffffffffu, ps[i], 2);
        po[i] += __shfl_xor_sync(0xffffffffu, po[i], 1);
        po[i] += __shfl_xor_sync(0xffffffffu, po[i], 2);
        if ((lane & 3) == 0) {
            atomicAdd(&g_logit[rows[i]], ps[i]);
            atomicAdd(&g_logit[NE + rows[i]], po[i]);
        }
    }
}

// ---------------- segment softmax ----------------
__device__ __forceinline__ void atomicMaxF(float* addr, float v) {
    if (v >= 0.f) atomicMax((int*)addr, __float_as_int(v));
    else          atomicMin((unsigned int*)addr, __float_as_uint(v));
}

__global__ void segmax_kernel(const int* __restrict__ sub, const int* __restrict__ obj) {
    int e = blockIdx.x * blockDim.x + threadIdx.x;
    if (e >= NE) return;
    atomicMaxF(&g_nmax[sub[e]], g_logit[e]);
    atomicMaxF(&g_nmax[NB + obj[e]], g_logit[NE + e]);
}

__global__ void expsum_kernel(const int* __restrict__ sub, const int* __restrict__ obj) {
    int e = blockIdx.x * blockDim.x + threadIdx.x;
    if (e >= NE) return;
    int s = sub[e], o = obj[e];
    float es = expf(g_logit[e] - g_nmax[s]);
    float eo = expf(g_logit[NE + e] - g_nmax[NB + o]);
    g_alpha[e] = es;
    g_alpha[NE + e] = eo;
    atomicAdd(&g_denom[s], es);
    atomicAdd(&g_denom[NB + o], eo);
}

__global__ void salpha_kernel() {
    int i = blockIdx.x * blockDim.x + threadIdx.x;
    if (i >= 2 * NB) return;
    float d = g_denom[i];
    g_salpha[i] = d / (d + 1e-9f);
}

// ---------------- launch ----------------
static inline void splith(const float* src, __half* hi, long n) {
    splith_kernel<<<(int)((n / 4 + 255) / 256), 256>>>(src, hi, n);
}

extern "C" void kernel_launch(void* const* d_in, const int* in_sizes, int n_in,
                              void* d_out, int out_size) {
    const float* box_feats = (const float*)d_in[0];
    const float* rel_feats = (const float*)d_in[1];
    const int*   edge_sub  = (const int*)d_in[2];
    const int*   edge_obj  = (const int*)d_in[3];
    const float* W_box  = (const float*)d_in[4];
    const float* b_box  = (const float*)d_in[5];
    const float* W_sub  = (const float*)d_in[6];
    const float* b_sub  = (const float*)d_in[7];
    const float* W_obj  = (const float*)d_in[8];
    const float* b_obj  = (const float*)d_in[9];
    const float* Wa_box = (const float*)d_in[10];
    const float* Wa_rel = (const float*)d_in[11];
    const float* b_a1   = (const float*)d_in[12];
    const float* Wa2    = (const float*)d_in[13];
    const float* b_a2   = (const float*)d_in[14];
    float* out = (float*)d_out;

    float* box_att;
    cudaGetSymbolAddress((void**)&box_att, g_box_att);

    __half *relh, *boxh, *wsh, *Wabh, *Warh, *WC;
    cudaGetSymbolAddress((void**)&relh, g_relh);
    cudaGetSymbolAddress((void**)&boxh, g_boxh);
    cudaGetSymbolAddress((void**)&wsh,  g_wsh);
    cudaGetSymbolAddress((void**)&Wabh, g_Wabh);
    cudaGetSymbolAddress((void**)&Warh, g_Warh);
    cudaGetSymbolAddress((void**)&WC,   g_WC);

    init_kernel<<<512, 256>>>(b_a2);

    // CSR build (independent of logits — run early)
    count_kernel<<<(NE + 255) / 256, 256>>>(edge_sub, edge_obj);
    scan_kernel<<<1, 1024>>>();
    fill_kernel<<<(NE + 255) / 256, 256>>>(edge_sub, edge_obj);

    // splits (all hi-only fp16)
    splith(box_feats, boxh, (long)NB * OD);
    splith(rel_feats, relh, (long)NE * FD);
    splith(Wa_box, Wabh, (long)OD * OD);
    splith(Wa_rel, Warh, (long)FD * OD);
    splith(W_box,  WC,                                (long)OD * OD);
    splith(W_sub,  WC + (size_t)OD * OD,              (long)FD * OD);
    splith(W_obj,  WC + (size_t)(OD + FD) * OD,       (long)FD * OD);

    // box_att = box_feats @ Wa_box   (fp16, logit path)
    mma_gemm<<<dim3(OD / 128, NB / 128), 256>>>(boxh, Wabh, box_att, NB, OD, OD);

    // fused: logits += partial dot over relu(rel@Wa_rel + box_att[idx] + b_a1) . Wa2
    rel_logit_gemm<<<dim3(OD / 256, NE / 128), 512>>>(
        relh, Warh, edge_sub, edge_obj, b_a1, Wa2, NE, OD, FD);

    segmax_kernel<<<(NE + 255) / 256, 256>>>(edge_sub, edge_obj);
    expsum_kernel<<<(NE + 255) / 256, 256>>>(edge_sub, edge_obj);
    salpha_kernel<<<(2 * NB + 255) / 256, 256>>>();

    // CSR gather: wsh = fp16( segment_sum(alpha * relh) ), no atomics
    gather_kernel<<<2 * NB, 256>>>();

    // fused value GEMM: out = relu(bias + [box | wsum_s | wsum_o] @ [W_box; W_sub; W_obj])
    value_gemm<<<dim3(OD / 128, NB / 128), 256>>>(
        boxh, wsh, WC, b_box, b_sub, b_obj, out);
}